// round 2
// baseline (speedup 1.0000x reference)
#include <cuda_runtime.h>
#include <cstdint>

// Problem constants
#define BATCH 8
#define SEQ   2048
#define EMB   1024
#define HS    64
#define MTOT  (BATCH * SEQ)   // 16384

// Scratch for projected q, k, v  (static __device__ arrays: allocation-guard safe)
__device__ float g_q[MTOT * HS];
__device__ float g_k[MTOT * HS];
__device__ float g_v[MTOT * HS];

// ---------------------------------------------------------------------------
// Kernel 1: fused QKV projection.  out[m][n] = sum_e x[m][e] * W[n][e] + b[n]
// M = 16384, N = 64 (per projection), K = 1024.
// grid = (M/64, 3), block = 256 threads (16x16, 4x4 micro-tile)
// ---------------------------------------------------------------------------
__global__ __launch_bounds__(256) void proj_kernel(
    const float* __restrict__ x,
    const float* __restrict__ Wq, const float* __restrict__ bq,
    const float* __restrict__ Wk, const float* __restrict__ bk,
    const float* __restrict__ Wv, const float* __restrict__ bv)
{
    __shared__ float Xs[16][68];   // [e_local][m] transposed x tile
    __shared__ float Ws[16][68];   // [e_local][n] transposed W tile

    const int which = blockIdx.y;
    const float* __restrict__ Wp = (which == 0) ? Wq : (which == 1 ? Wk : Wv);
    const float* __restrict__ bp = (which == 0) ? bq : (which == 1 ? bk : bv);
    float* outp = (which == 0) ? g_q : (which == 1 ? g_k : g_v);

    const int tid = threadIdx.x;
    const int tx = tid & 15;       // n micro-tile index
    const int ty = tid >> 4;       // m micro-tile index
    const int m0 = blockIdx.x * 64;

    const int lrow = tid >> 2;           // 0..63 (m or n row for loads)
    const int lcol = (tid & 3) * 4;      // 0,4,8,12 within BK=16

    const float* xg = x  + (size_t)(m0 + lrow) * EMB + lcol;
    const float* wg = Wp + (size_t)lrow * EMB + lcol;

    float acc[4][4] = {};

    for (int e0 = 0; e0 < EMB; e0 += 16) {
        float4 xv = *(const float4*)(xg + e0);
        float4 wv = *(const float4*)(wg + e0);
        __syncthreads();
        Xs[lcol + 0][lrow] = xv.x; Xs[lcol + 1][lrow] = xv.y;
        Xs[lcol + 2][lrow] = xv.z; Xs[lcol + 3][lrow] = xv.w;
        Ws[lcol + 0][lrow] = wv.x; Ws[lcol + 1][lrow] = wv.y;
        Ws[lcol + 2][lrow] = wv.z; Ws[lcol + 3][lrow] = wv.w;
        __syncthreads();

#pragma unroll
        for (int kk = 0; kk < 16; kk++) {
            float4 a4 = *(const float4*)&Xs[kk][ty * 4];
            float4 b4 = *(const float4*)&Ws[kk][tx * 4];
            float av[4] = {a4.x, a4.y, a4.z, a4.w};
            float bv4[4] = {b4.x, b4.y, b4.z, b4.w};
#pragma unroll
            for (int i = 0; i < 4; i++)
#pragma unroll
                for (int j = 0; j < 4; j++)
                    acc[i][j] += av[i] * bv4[j];
        }
    }

#pragma unroll
    for (int i = 0; i < 4; i++) {
        float4 o;
        o.x = acc[i][0] + bp[tx * 4 + 0];
        o.y = acc[i][1] + bp[tx * 4 + 1];
        o.z = acc[i][2] + bp[tx * 4 + 2];
        o.w = acc[i][3] + bp[tx * 4 + 3];
        *(float4*)&outp[(size_t)(m0 + ty * 4 + i) * HS + tx * 4] = o;
    }
}

// ---------------------------------------------------------------------------
// Kernel 2: causal flash attention, fp32.
// BM = BN = 64, 256 threads (16x16 grid of 4x4 micro-tiles).
// Shared: Qt [e][m] (stride 68), KP (Kt [e][n] then P^T [k][m], stride 68),
//         Vs [k][h] (stride 64).  Total 51200 B dynamic smem.
// grid = (SEQ/64, BATCH); q-tile index reversed so heaviest blocks go first.
// ---------------------------------------------------------------------------
#define QT_STRIDE 68
#define SMEM_FLOATS (2 * 64 * QT_STRIDE + 64 * 64)
#define SMEM_BYTES  (SMEM_FLOATS * 4)

__global__ __launch_bounds__(256) void attn_kernel(float* __restrict__ out)
{
    extern __shared__ float sm[];
    float* Qt = sm;                    // [64][68]  Q transposed: Qt[e][m]
    float* KP = sm + 64 * QT_STRIDE;   // [64][68]  Kt[e][n], reused as P^T[k][m]
    float* Vs = sm + 2 * 64 * QT_STRIDE; // [64][64] Vs[k][h]

    const int b  = blockIdx.y;
    const int qt = gridDim.x - 1 - blockIdx.x;  // reversed: longest work first
    const int q0 = qt * 64;
    const int tid = threadIdx.x;
    const int tx = tid & 15;
    const int ty = tid >> 4;

    const float* qg = g_q + ((size_t)b * SEQ + q0) * HS;
    const float* kg = g_k + (size_t)b * SEQ * HS;
    const float* vg = g_v + (size_t)b * SEQ * HS;

    // Load Q tile (transposed into Qt[e][m])
#pragma unroll
    for (int i = 0; i < 16; i++) {
        int idx = tid + i * 256;
        int m = idx >> 6, e = idx & 63;
        Qt[e * QT_STRIDE + m] = qg[idx];
    }

    float mrow[4], lsum[4], o[4][4];
#pragma unroll
    for (int i = 0; i < 4; i++) {
        mrow[i] = -1e30f;
        lsum[i] = 0.0f;
#pragma unroll
        for (int j = 0; j < 4; j++) o[i][j] = 0.0f;
    }

    for (int kt = 0; kt <= qt; kt++) {
        const int k0 = kt * 64;

        __syncthreads();  // previous P/V reads done; also orders Q-load (first iter)
        // Load K tile (transposed) and V tile (natural)
#pragma unroll
        for (int i = 0; i < 16; i++) {
            int idx = tid + i * 256;
            int n = idx >> 6, e = idx & 63;
            KP[e * QT_STRIDE + n] = kg[k0 * HS + idx];
            Vs[idx]               = vg[k0 * HS + idx];
        }
        __syncthreads();

        // S = Q K^T  (per-thread 4x4)
        float s[4][4] = {};
#pragma unroll 8
        for (int e = 0; e < 64; e++) {
            float4 q4 = *(const float4*)&Qt[e * QT_STRIDE + ty * 4];
            float4 k4 = *(const float4*)&KP[e * QT_STRIDE + tx * 4];
            float qv[4] = {q4.x, q4.y, q4.z, q4.w};
            float kv[4] = {k4.x, k4.y, k4.z, k4.w};
#pragma unroll
            for (int i = 0; i < 4; i++)
#pragma unroll
                for (int j = 0; j < 4; j++)
                    s[i][j] += qv[i] * kv[j];
        }

        // Scale + causal mask (only needed on the diagonal tile: k0 == q0)
        const bool diag = (kt == qt);
#pragma unroll
        for (int i = 0; i < 4; i++)
#pragma unroll
            for (int j = 0; j < 4; j++) {
                s[i][j] *= 0.125f;   // 1/sqrt(64)
                if (diag && (tx * 4 + j > ty * 4 + i)) s[i][j] = -1e30f;
            }

        // Online softmax
        float mt[4], pt[4][4], lt[4], alpha[4];
#pragma unroll
        for (int i = 0; i < 4; i++) {
            float mv = fmaxf(fmaxf(s[i][0], s[i][1]), fmaxf(s[i][2], s[i][3]));
#pragma unroll
            for (int off = 8; off >= 1; off >>= 1)
                mv = fmaxf(mv, __shfl_xor_sync(0xffffffffu, mv, off, 16));
            mt[i] = mv;
        }
#pragma unroll
        for (int i = 0; i < 4; i++) {
            float mnew = fmaxf(mrow[i], mt[i]);
            alpha[i] = __expf(mrow[i] - mnew);
            float ls = 0.0f;
#pragma unroll
            for (int j = 0; j < 4; j++) {
                pt[i][j] = __expf(s[i][j] - mnew);
                ls += pt[i][j];
            }
#pragma unroll
            for (int off = 8; off >= 1; off >>= 1)
                ls += __shfl_xor_sync(0xffffffffu, ls, off, 16);
            lt[i] = ls;
            mrow[i] = mnew;
            lsum[i] = lsum[i] * alpha[i] + lt[i];
#pragma unroll
            for (int j = 0; j < 4; j++) o[i][j] *= alpha[i];
        }

        __syncthreads();  // all threads done reading Kt before overwriting with P
        // Store P transposed: P^T[k][m], k = tx*4+j, m = ty*4+i
#pragma unroll
        for (int i = 0; i < 4; i++)
#pragma unroll
            for (int j = 0; j < 4; j++)
                KP[(tx * 4 + j) * QT_STRIDE + ty * 4 + i] = pt[i][j];
        __syncthreads();

        // O += P V
#pragma unroll 8
        for (int k = 0; k < 64; k++) {
            float4 p4 = *(const float4*)&KP[k * QT_STRIDE + ty * 4];
            float4 v4 = *(const float4*)&Vs[k * 64 + tx * 4];
            float pv[4] = {p4.x, p4.y, p4.z, p4.w};
            float vv[4] = {v4.x, v4.y, v4.z, v4.w};
#pragma unroll
            for (int i = 0; i < 4; i++)
#pragma unroll
                for (int j = 0; j < 4; j++)
                    o[i][j] += pv[i] * vv[j];
        }
    }

    // Epilogue: normalize and store
#pragma unroll
    for (int i = 0; i < 4; i++) {
        float inv = 1.0f / lsum[i];
        float4 o4;
        o4.x = o[i][0] * inv;
        o4.y = o[i][1] * inv;
        o4.z = o[i][2] * inv;
        o4.w = o[i][3] * inv;
        *(float4*)&out[((size_t)b * SEQ + q0 + ty * 4 + i) * HS + tx * 4] = o4;
    }
}

// ---------------------------------------------------------------------------
// Launch
// ---------------------------------------------------------------------------
extern "C" void kernel_launch(void* const* d_in, const int* in_sizes, int n_in,
                              void* d_out, int out_size)
{
    const float* x  = (const float*)d_in[0];
    const float* Wq = (const float*)d_in[1];
    const float* bq = (const float*)d_in[2];
    const float* Wk = (const float*)d_in[3];
    const float* bk = (const float*)d_in[4];
    const float* Wv = (const float*)d_in[5];
    const float* bv = (const float*)d_in[6];
    float* out = (float*)d_out;

    dim3 gproj(MTOT / 64, 3);
    proj_kernel<<<gproj, 256>>>(x, Wq, bq, Wk, bk, Wv, bv);

    cudaFuncSetAttribute(attn_kernel,
                         cudaFuncAttributeMaxDynamicSharedMemorySize, SMEM_BYTES);
    dim3 gattn(SEQ / 64, BATCH);
    attn_kernel<<<gattn, 256, SMEM_BYTES>>>(out);
}

// round 3
// speedup vs baseline: 3.2618x; 3.2618x over previous
#include <cuda_runtime.h>
#include <cstdint>

#define BATCH 8
#define SEQ   2048
#define EMB   1024
#define HS    64
#define MTOT  (BATCH * SEQ)   // 16384

// Scratch for projected q, k, v
__device__ float g_q[MTOT * HS];
__device__ float g_k[MTOT * HS];
__device__ float g_v[MTOT * HS];

__device__ __forceinline__ float to_tf32(float x) {
    float y;
    asm("cvt.rna.tf32.f32 %0, %1;" : "=f"(y) : "f"(x));
    return y;
}

__device__ __forceinline__ void mma_tf32(float c[4], const unsigned a[4], const unsigned b[2]) {
    asm volatile(
        "mma.sync.aligned.m16n8k8.row.col.f32.tf32.tf32.f32 "
        "{%0,%1,%2,%3}, {%4,%5,%6,%7}, {%8,%9}, {%0,%1,%2,%3};"
        : "+f"(c[0]), "+f"(c[1]), "+f"(c[2]), "+f"(c[3])
        : "r"(a[0]), "r"(a[1]), "r"(a[2]), "r"(a[3]), "r"(b[0]), "r"(b[1]));
}

// ---------------------------------------------------------------------------
// Kernel 1: fused QKV projection (tf32 tensor cores).
// out[m][n] = sum_e x[m][e] * W[n][e] + b[n];  N = 192 (q|k|v), tile 64x192.
// 256 threads = 8 warps as 2(M) x 4(N); warp tile 32x48.
// ---------------------------------------------------------------------------
#define XPAD 36
__global__ __launch_bounds__(256) void proj_kernel(
    const float* __restrict__ x,
    const float* __restrict__ Wq, const float* __restrict__ bq,
    const float* __restrict__ Wk, const float* __restrict__ bk,
    const float* __restrict__ Wv, const float* __restrict__ bv)
{
    __shared__ float Xs[64][XPAD];    // [m][k], tf32 values
    __shared__ float Ws[192][XPAD];   // [n][k], tf32 values
    __shared__ float sbias[192];

    const int tid  = threadIdx.x;
    const int warp = tid >> 5;
    const int lane = tid & 31;
    const int g    = lane >> 2;      // 0..7
    const int t4   = lane & 3;       // 0..3
    const int mw   = warp >> 2;      // 0..1
    const int nw   = warp & 3;       // 0..3
    const int m0   = blockIdx.x * 64;

    if (tid < 192)
        sbias[tid] = (tid < 64) ? bq[tid] : (tid < 128 ? bk[tid - 64] : bv[tid - 128]);

    const float* wsrc[3] = {Wq, Wk, Wv};

    float acc[2][6][4];
#pragma unroll
    for (int i = 0; i < 2; i++)
#pragma unroll
        for (int j = 0; j < 6; j++)
#pragma unroll
            for (int c = 0; c < 4; c++) acc[i][j][c] = 0.0f;

    for (int e0 = 0; e0 < EMB; e0 += 32) {
        __syncthreads();
        // Load X tile: 64 rows x 32 cols = 512 float4 granules / 256 thr = 2
#pragma unroll
        for (int i = 0; i < 2; i++) {
            int id = tid + i * 256;
            int row = id >> 3, col = (id & 7) * 4;
            float4 v = *(const float4*)&x[(size_t)(m0 + row) * EMB + e0 + col];
            Xs[row][col + 0] = to_tf32(v.x); Xs[row][col + 1] = to_tf32(v.y);
            Xs[row][col + 2] = to_tf32(v.z); Xs[row][col + 3] = to_tf32(v.w);
        }
        // Load W tile: 192 rows x 32 cols = 1536 granules / 256 = 6
#pragma unroll
        for (int i = 0; i < 6; i++) {
            int id = tid + i * 256;
            int n = id >> 3, col = (id & 7) * 4;
            const float* wr = wsrc[n >> 6] + (size_t)(n & 63) * EMB + e0 + col;
            float4 v = *(const float4*)wr;
            Ws[n][col + 0] = to_tf32(v.x); Ws[n][col + 1] = to_tf32(v.y);
            Ws[n][col + 2] = to_tf32(v.z); Ws[n][col + 3] = to_tf32(v.w);
        }
        __syncthreads();

#pragma unroll
        for (int ks = 0; ks < 4; ks++) {
            int kc = ks * 8 + t4;
            unsigned a[2][4];
#pragma unroll
            for (int mt = 0; mt < 2; mt++) {
                int r = mw * 32 + mt * 16 + g;
                a[mt][0] = __float_as_uint(Xs[r][kc]);
                a[mt][1] = __float_as_uint(Xs[r + 8][kc]);
                a[mt][2] = __float_as_uint(Xs[r][kc + 4]);
                a[mt][3] = __float_as_uint(Xs[r + 8][kc + 4]);
            }
#pragma unroll
            for (int nt = 0; nt < 6; nt++) {
                int n = nw * 48 + nt * 8 + g;
                unsigned b[2];
                b[0] = __float_as_uint(Ws[n][kc]);
                b[1] = __float_as_uint(Ws[n][kc + 4]);
                mma_tf32(acc[0][nt], a[0], b);
                mma_tf32(acc[1][nt], a[1], b);
            }
        }
    }

    // Epilogue: bias + scatter to g_q/g_k/g_v
#pragma unroll
    for (int mt = 0; mt < 2; mt++) {
        int r0 = m0 + mw * 32 + mt * 16 + g;
#pragma unroll
        for (int nt = 0; nt < 6; nt++) {
            int ncol = nw * 48 + nt * 8 + t4 * 2;
            float* outp = (ncol < 64) ? g_q : (ncol < 128 ? g_k : g_v);
            int nl = ncol & 63;
            float b0 = sbias[ncol], b1 = sbias[ncol + 1];
            float2 v0 = make_float2(acc[mt][nt][0] + b0, acc[mt][nt][1] + b1);
            float2 v1 = make_float2(acc[mt][nt][2] + b0, acc[mt][nt][3] + b1);
            *(float2*)&outp[(size_t)r0 * HS + nl]       = v0;
            *(float2*)&outp[(size_t)(r0 + 8) * HS + nl] = v1;
        }
    }
}

// ---------------------------------------------------------------------------
// Kernel 2: causal flash attention, tf32 tensor cores (FA2 fragment style).
// BM = BN = 64, 128 threads = 4 warps; warp w owns Q rows [w*16, w*16+16).
// Smem: Qs/Ps [64][68], Ks [64][68], Vs [64][72].
// ---------------------------------------------------------------------------
#define KPAD 68
#define VPAD 72
#define ATTN_SMEM ((2 * 64 * KPAD + 64 * VPAD) * 4)

__global__ __launch_bounds__(128) void attn_kernel(float* __restrict__ out)
{
    extern __shared__ float sm[];
    float* Qs = sm;                    // [64][68]; reused as P (per-warp rows)
    float* Ks = sm + 64 * KPAD;        // [64][68]
    float* Vs = sm + 2 * 64 * KPAD;    // [64][72]

    const int b   = blockIdx.y;
    const int qt  = gridDim.x - 1 - blockIdx.x;   // longest work first
    const int q0  = qt * 64;
    const int tid = threadIdx.x;
    const int warp = tid >> 5;
    const int lane = tid & 31;
    const int g  = lane >> 2;
    const int t4 = lane & 3;

    const float* qg = g_q + ((size_t)b * SEQ + q0) * HS;
    const float* kg = g_k + (size_t)b * SEQ * HS;
    const float* vg = g_v + (size_t)b * SEQ * HS;

    // Stage Q (tf32) and pull fragments into registers
#pragma unroll
    for (int i = 0; i < 8; i++) {
        int id = tid + i * 128;
        int row = id >> 4, col = (id & 15) * 4;
        float4 v = *(const float4*)&qg[row * HS + col];
        Qs[row * KPAD + col + 0] = to_tf32(v.x);
        Qs[row * KPAD + col + 1] = to_tf32(v.y);
        Qs[row * KPAD + col + 2] = to_tf32(v.z);
        Qs[row * KPAD + col + 3] = to_tf32(v.w);
    }
    __syncthreads();

    const int qr = warp * 16 + g;     // local row (first of the pair)
    unsigned qf[8][4];
#pragma unroll
    for (int ks = 0; ks < 8; ks++) {
        int kc = ks * 8 + t4;
        qf[ks][0] = __float_as_uint(Qs[qr * KPAD + kc]);
        qf[ks][1] = __float_as_uint(Qs[(qr + 8) * KPAD + kc]);
        qf[ks][2] = __float_as_uint(Qs[qr * KPAD + kc + 4]);
        qf[ks][3] = __float_as_uint(Qs[(qr + 8) * KPAD + kc + 4]);
    }

    float o[8][4];
#pragma unroll
    for (int nt = 0; nt < 8; nt++)
#pragma unroll
        for (int c = 0; c < 4; c++) o[nt][c] = 0.0f;
    float mrow0 = -1e30f, mrow1 = -1e30f, lsum0 = 0.0f, lsum1 = 0.0f;

    for (int kt = 0; kt <= qt; kt++) {
        __syncthreads();   // prior PV reads of Vs done; Q frags loaded (iter 0)
#pragma unroll
        for (int i = 0; i < 8; i++) {
            int id = tid + i * 128;
            int row = id >> 4, col = (id & 15) * 4;
            float4 kv = *(const float4*)&kg[(kt * 64 + row) * HS + col];
            Ks[row * KPAD + col + 0] = to_tf32(kv.x);
            Ks[row * KPAD + col + 1] = to_tf32(kv.y);
            Ks[row * KPAD + col + 2] = to_tf32(kv.z);
            Ks[row * KPAD + col + 3] = to_tf32(kv.w);
            float4 vv = *(const float4*)&vg[(kt * 64 + row) * HS + col];
            Vs[row * VPAD + col + 0] = to_tf32(vv.x);
            Vs[row * VPAD + col + 1] = to_tf32(vv.y);
            Vs[row * VPAD + col + 2] = to_tf32(vv.z);
            Vs[row * VPAD + col + 3] = to_tf32(vv.w);
        }
        __syncthreads();

        // S = Q K^T   (warp: 16 x 64)
        float s[8][4];
#pragma unroll
        for (int nt = 0; nt < 8; nt++)
#pragma unroll
            for (int c = 0; c < 4; c++) s[nt][c] = 0.0f;
#pragma unroll
        for (int ks = 0; ks < 8; ks++) {
            int kc = ks * 8 + t4;
#pragma unroll
            for (int nt = 0; nt < 8; nt++) {
                int n = nt * 8 + g;
                unsigned bfr[2];
                bfr[0] = __float_as_uint(Ks[n * KPAD + kc]);
                bfr[1] = __float_as_uint(Ks[n * KPAD + kc + 4]);
                mma_tf32(s[nt], qf[ks], bfr);
            }
        }

        // scale + causal mask (diagonal tile only)
        const bool diag = (kt == qt);
#pragma unroll
        for (int nt = 0; nt < 8; nt++) {
            int col = nt * 8 + t4 * 2;
#pragma unroll
            for (int c = 0; c < 4; c++) {
                int cc = col + (c & 1);
                int rr = qr + ((c >> 1) << 3);   // qr or qr+8
                s[nt][c] *= 0.125f;
                if (diag && cc > rr) s[nt][c] = -1e30f;
            }
        }

        // online softmax: rows qr (c0,c1) and qr+8 (c2,c3); quad = lanes sharing g
        float mt0 = -1e30f, mt1 = -1e30f;
#pragma unroll
        for (int nt = 0; nt < 8; nt++) {
            mt0 = fmaxf(mt0, fmaxf(s[nt][0], s[nt][1]));
            mt1 = fmaxf(mt1, fmaxf(s[nt][2], s[nt][3]));
        }
#pragma unroll
        for (int off = 1; off <= 2; off <<= 1) {
            mt0 = fmaxf(mt0, __shfl_xor_sync(0xffffffffu, mt0, off));
            mt1 = fmaxf(mt1, __shfl_xor_sync(0xffffffffu, mt1, off));
        }
        float mnew0 = fmaxf(mrow0, mt0), mnew1 = fmaxf(mrow1, mt1);
        float alpha0 = __expf(mrow0 - mnew0), alpha1 = __expf(mrow1 - mnew1);
        float lt0 = 0.0f, lt1 = 0.0f;
#pragma unroll
        for (int nt = 0; nt < 8; nt++) {
            s[nt][0] = __expf(s[nt][0] - mnew0);
            s[nt][1] = __expf(s[nt][1] - mnew0);
            s[nt][2] = __expf(s[nt][2] - mnew1);
            s[nt][3] = __expf(s[nt][3] - mnew1);
            lt0 += s[nt][0] + s[nt][1];
            lt1 += s[nt][2] + s[nt][3];
        }
#pragma unroll
        for (int off = 1; off <= 2; off <<= 1) {
            lt0 += __shfl_xor_sync(0xffffffffu, lt0, off);
            lt1 += __shfl_xor_sync(0xffffffffu, lt1, off);
        }
        mrow0 = mnew0; mrow1 = mnew1;
        lsum0 = lsum0 * alpha0 + lt0;
        lsum1 = lsum1 * alpha1 + lt1;
#pragma unroll
        for (int nt = 0; nt < 8; nt++) {
            o[nt][0] *= alpha0; o[nt][1] *= alpha0;
            o[nt][2] *= alpha1; o[nt][3] *= alpha1;
        }

        // Store P (tf32) into this warp's private rows of the Q buffer
        float* Pw = Qs + (warp * 16) * KPAD;
#pragma unroll
        for (int nt = 0; nt < 8; nt++) {
            int col = nt * 8 + t4 * 2;
            Pw[g * KPAD + col]           = to_tf32(s[nt][0]);
            Pw[g * KPAD + col + 1]       = to_tf32(s[nt][1]);
            Pw[(g + 8) * KPAD + col]     = to_tf32(s[nt][2]);
            Pw[(g + 8) * KPAD + col + 1] = to_tf32(s[nt][3]);
        }
        __syncwarp();

        // O += P V   (warp: 16 x 64, K over 64 keys)
#pragma unroll
        for (int ks = 0; ks < 8; ks++) {
            int kc = ks * 8 + t4;
            unsigned pa[4];
            pa[0] = __float_as_uint(Pw[g * KPAD + kc]);
            pa[1] = __float_as_uint(Pw[(g + 8) * KPAD + kc]);
            pa[2] = __float_as_uint(Pw[g * KPAD + kc + 4]);
            pa[3] = __float_as_uint(Pw[(g + 8) * KPAD + kc + 4]);
#pragma unroll
            for (int nt = 0; nt < 8; nt++) {
                int nh = nt * 8 + g;
                unsigned vb[2];
                vb[0] = __float_as_uint(Vs[kc * VPAD + nh]);
                vb[1] = __float_as_uint(Vs[(kc + 4) * VPAD + nh]);
                mma_tf32(o[nt], pa, vb);
            }
        }
    }

    // Epilogue
    float inv0 = 1.0f / lsum0, inv1 = 1.0f / lsum1;
    size_t row0 = (size_t)b * SEQ + q0 + qr;
#pragma unroll
    for (int nt = 0; nt < 8; nt++) {
        int col = nt * 8 + t4 * 2;
        *(float2*)&out[row0 * HS + col] =
            make_float2(o[nt][0] * inv0, o[nt][1] * inv0);
        *(float2*)&out[(row0 + 8) * HS + col] =
            make_float2(o[nt][2] * inv1, o[nt][3] * inv1);
    }
}

// ---------------------------------------------------------------------------
extern "C" void kernel_launch(void* const* d_in, const int* in_sizes, int n_in,
                              void* d_out, int out_size)
{
    const float* x  = (const float*)d_in[0];
    const float* Wq = (const float*)d_in[1];
    const float* bq = (const float*)d_in[2];
    const float* Wk = (const float*)d_in[3];
    const float* bk = (const float*)d_in[4];
    const float* Wv = (const float*)d_in[5];
    const float* bv = (const float*)d_in[6];
    float* out = (float*)d_out;

    proj_kernel<<<MTOT / 64, 256>>>(x, Wq, bq, Wk, bk, Wv, bv);

    cudaFuncSetAttribute(attn_kernel,
                         cudaFuncAttributeMaxDynamicSharedMemorySize, ATTN_SMEM);
    dim3 gattn(SEQ / 64, BATCH);
    attn_kernel<<<gattn, 128, ATTN_SMEM>>>(out);
}

// round 6
// speedup vs baseline: 3.7810x; 1.1592x over previous
#include <cuda_runtime.h>
#include <cstdint>

#define BATCH 8
#define SEQ   2048
#define EMB   1024
#define HS    64
#define MTOT  (BATCH * SEQ)   // 16384
#define NQT   (SEQ / 64)      // 32 q-tiles per batch

// Scratch
__device__ float g_q[MTOT * HS];
__device__ float g_k[MTOT * HS];
__device__ float g_v[MTOT * HS];
__device__ float g_opart[2 * MTOT * HS];   // unnormalized partial O per split
__device__ float g_mpart[2 * MTOT];        // running max (log2 domain)
__device__ float g_lpart[2 * MTOT];        // running sum

__device__ __forceinline__ float to_tf32(float x) {
    float y;
    asm("cvt.rna.tf32.f32 %0, %1;" : "=f"(y) : "f"(x));
    return y;
}
__device__ __forceinline__ unsigned tf32u(float x) { return __float_as_uint(to_tf32(x)); }

__device__ __forceinline__ float fast_exp2(float x) {
    float y;
    asm("ex2.approx.ftz.f32 %0, %1;" : "=f"(y) : "f"(x));
    return y;
}

__device__ __forceinline__ void mma_tf32(float c[4], const unsigned a[4], const unsigned b[2]) {
    asm volatile(
        "mma.sync.aligned.m16n8k8.row.col.f32.tf32.tf32.f32 "
        "{%0,%1,%2,%3}, {%4,%5,%6,%7}, {%8,%9}, {%0,%1,%2,%3};"
        : "+f"(c[0]), "+f"(c[1]), "+f"(c[2]), "+f"(c[3])
        : "r"(a[0]), "r"(a[1]), "r"(a[2]), "r"(a[3]), "r"(b[0]), "r"(b[1]));
}

__device__ __forceinline__ void cp16(float* dst_smem, const float* src) {
    unsigned d = (unsigned)__cvta_generic_to_shared(dst_smem);
    asm volatile("cp.async.cg.shared.global [%0], [%1], 16;" :: "r"(d), "l"(src));
}
#define CP_COMMIT() asm volatile("cp.async.commit_group;")
#define CP_WAIT1()  asm volatile("cp.async.wait_group 1;")

// ---------------------------------------------------------------------------
// Kernel 1: fused QKV projection, tf32 MMA, cp.async double-buffered.
// tile 64(M) x 192(N=q|k|v), BK=32. 256 threads = 8 warps (2M x 4N).
// ---------------------------------------------------------------------------
#define XPAD 36
#define PROJ_SMEM ((2 * 64 * XPAD + 2 * 192 * XPAD + 192) * 4)

__global__ __launch_bounds__(256) void proj_kernel(
    const float* __restrict__ x,
    const float* __restrict__ Wq, const float* __restrict__ bq,
    const float* __restrict__ Wk, const float* __restrict__ bk,
    const float* __restrict__ Wv, const float* __restrict__ bv)
{
    extern __shared__ float sm[];
    float* Xs    = sm;                                  // [2][64][36]
    float* Wsm   = sm + 2 * 64 * XPAD;                  // [2][192][36]
    float* sbias = sm + 2 * 64 * XPAD + 2 * 192 * XPAD; // [192]

    const int tid  = threadIdx.x;
    const int warp = tid >> 5;
    const int lane = tid & 31;
    const int g    = lane >> 2;
    const int t4   = lane & 3;
    const int mw   = warp >> 2;
    const int nw   = warp & 3;
    const int m0   = blockIdx.x * 64;

    if (tid < 192)
        sbias[tid] = (tid < 64) ? bq[tid] : (tid < 128 ? bk[tid - 64] : bv[tid - 128]);

    const float* wsrc[3] = {Wq, Wk, Wv};

    // stage issuer: e0 = stage*32 into buffer bs
    auto issue = [&](int stage, int bs) {
        const int e0 = stage * 32;
        float* Xb = Xs + bs * 64 * XPAD;
        float* Wb = Wsm + bs * 192 * XPAD;
#pragma unroll
        for (int i = 0; i < 2; i++) {
            int id = tid + i * 256;
            int row = id >> 3, col = (id & 7) * 4;
            cp16(&Xb[row * XPAD + col], &x[(size_t)(m0 + row) * EMB + e0 + col]);
        }
#pragma unroll
        for (int i = 0; i < 6; i++) {
            int id = tid + i * 256;
            int n = id >> 3, col = (id & 7) * 4;
            cp16(&Wb[n * XPAD + col], wsrc[n >> 6] + (size_t)(n & 63) * EMB + e0 + col);
        }
    };

    float acc[2][6][4];
#pragma unroll
    for (int i = 0; i < 2; i++)
#pragma unroll
        for (int j = 0; j < 6; j++)
#pragma unroll
            for (int c = 0; c < 4; c++) acc[i][j][c] = 0.0f;

    issue(0, 0);
    CP_COMMIT();

    const int NST = EMB / 32;   // 32 stages
    for (int t = 0; t < NST; t++) {
        const int buf = t & 1;
        __syncthreads();               // everyone done computing on buf^1
        if (t + 1 < NST) issue(t + 1, buf ^ 1);
        CP_COMMIT();
        CP_WAIT1();                    // stage t data resident
        __syncthreads();

        const float* Xb = Xs + buf * 64 * XPAD;
        const float* Wb = Wsm + buf * 192 * XPAD;
#pragma unroll
        for (int ks = 0; ks < 4; ks++) {
            int kc = ks * 8 + t4;
            unsigned a[2][4];
#pragma unroll
            for (int mt = 0; mt < 2; mt++) {
                int r = mw * 32 + mt * 16 + g;
                a[mt][0] = tf32u(Xb[r * XPAD + kc]);
                a[mt][1] = tf32u(Xb[(r + 8) * XPAD + kc]);
                a[mt][2] = tf32u(Xb[r * XPAD + kc + 4]);
                a[mt][3] = tf32u(Xb[(r + 8) * XPAD + kc + 4]);
            }
#pragma unroll
            for (int nt = 0; nt < 6; nt++) {
                int n = nw * 48 + nt * 8 + g;
                unsigned b[2];
                b[0] = tf32u(Wb[n * XPAD + kc]);
                b[1] = tf32u(Wb[n * XPAD + kc + 4]);
                mma_tf32(acc[0][nt], a[0], b);
                mma_tf32(acc[1][nt], a[1], b);
            }
        }
    }

#pragma unroll
    for (int mt = 0; mt < 2; mt++) {
        int r0 = m0 + mw * 32 + mt * 16 + g;
#pragma unroll
        for (int nt = 0; nt < 6; nt++) {
            int ncol = nw * 48 + nt * 8 + t4 * 2;
            float* outp = (ncol < 64) ? g_q : (ncol < 128 ? g_k : g_v);
            int nl = ncol & 63;
            float b0 = sbias[ncol], b1 = sbias[ncol + 1];
            *(float2*)&outp[(size_t)r0 * HS + nl] =
                make_float2(acc[mt][nt][0] + b0, acc[mt][nt][1] + b1);
            *(float2*)&outp[(size_t)(r0 + 8) * HS + nl] =
                make_float2(acc[mt][nt][2] + b0, acc[mt][nt][3] + b1);
        }
    }
}

// ---------------------------------------------------------------------------
// Kernel 2: causal flash attention partials, tf32 MMA, split-KV 2-way,
// cp.async double-buffered K/V.  128 threads = 4 warps, BM=BN=64.
// Softmax in log2 domain (0.125*log2e folded into Q).
// ---------------------------------------------------------------------------
#define KPAD 68
#define VPAD 72
#define ATTN_SMEM ((64 * KPAD + 2 * 64 * KPAD + 2 * 64 * VPAD) * 4)

__global__ __launch_bounds__(128) void attn_part_kernel()
{
    extern __shared__ float sm[];
    float* Qs = sm;                         // [64][68]; reused per-warp as P
    float* Ks = sm + 64 * KPAD;             // [2][64][68]
    float* Vs = sm + 3 * 64 * KPAD;         // [2][64][72]

    const int b  = blockIdx.y;
    const int bx = blockIdx.x;
    const int qt = NQT - 1 - (bx >> 1);     // large tiles first
    const int s  = bx & 1;
    const int n  = qt + 1;
    const int h0 = (n + 1) >> 1;
    const int lo = s ? h0 : 0;
    const int hi = s ? n : h0;
    const int q0 = qt * 64;
    const int tid  = threadIdx.x;
    const int warp = tid >> 5;
    const int lane = tid & 31;
    const int g  = lane >> 2;
    const int t4 = lane & 3;

    float* opart = g_opart + ((size_t)s * MTOT + (size_t)b * SEQ + q0) * HS;
    float* mpart = g_mpart + s * MTOT + b * SEQ + q0;
    float* lpart = g_lpart + s * MTOT + b * SEQ + q0;

    if (lo >= hi) {   // empty split (qt==0, s==1)
        for (int i = tid; i < 64 * HS; i += 128) opart[i] = 0.0f;
        if (tid < 64) { mpart[tid] = -1e30f; lpart[tid] = 0.0f; }
        return;
    }

    const float* qg = g_q + ((size_t)b * SEQ + q0) * HS;
    const float* kg = g_k + (size_t)b * SEQ * HS;
    const float* vg = g_v + (size_t)b * SEQ * HS;

    const float qscale = 0.125f * 1.44269504f;  // 1/sqrt(64) * log2(e)

    // Stage Q (scaled, tf32)
#pragma unroll
    for (int i = 0; i < 8; i++) {
        int id = tid + i * 128;
        int row = id >> 4, col = (id & 15) * 4;
        float4 v = *(const float4*)&qg[row * HS + col];
        Qs[row * KPAD + col + 0] = to_tf32(v.x * qscale);
        Qs[row * KPAD + col + 1] = to_tf32(v.y * qscale);
        Qs[row * KPAD + col + 2] = to_tf32(v.z * qscale);
        Qs[row * KPAD + col + 3] = to_tf32(v.w * qscale);
    }
    __syncthreads();

    const int qr = warp * 16 + g;
    unsigned qf[8][4];
#pragma unroll
    for (int ks = 0; ks < 8; ks++) {
        int kc = ks * 8 + t4;
        qf[ks][0] = __float_as_uint(Qs[qr * KPAD + kc]);
        qf[ks][1] = __float_as_uint(Qs[(qr + 8) * KPAD + kc]);
        qf[ks][2] = __float_as_uint(Qs[qr * KPAD + kc + 4]);
        qf[ks][3] = __float_as_uint(Qs[(qr + 8) * KPAD + kc + 4]);
    }

    auto issue = [&](int kt, int bs) {
        float* Kb = Ks + bs * 64 * KPAD;
        float* Vb = Vs + bs * 64 * VPAD;
#pragma unroll
        for (int i = 0; i < 8; i++) {
            int id = tid + i * 128;
            int row = id >> 4, col = (id & 15) * 4;
            cp16(&Kb[row * KPAD + col], &kg[(size_t)(kt * 64 + row) * HS + col]);
            cp16(&Vb[row * VPAD + col], &vg[(size_t)(kt * 64 + row) * HS + col]);
        }
    };

    float o[8][4];
#pragma unroll
    for (int nt = 0; nt < 8; nt++)
#pragma unroll
        for (int c = 0; c < 4; c++) o[nt][c] = 0.0f;
    float mrow0 = -1e30f, mrow1 = -1e30f, lsum0 = 0.0f, lsum1 = 0.0f;

    issue(lo, 0);
    CP_COMMIT();

    for (int kt = lo; kt < hi; kt++) {
        const int buf = (kt - lo) & 1;
        __syncthreads();                       // all done with buf^1 compute
        if (kt + 1 < hi) issue(kt + 1, buf ^ 1);
        CP_COMMIT();
        CP_WAIT1();                            // tile kt resident
        __syncthreads();

        const float* Kb = Ks + buf * 64 * KPAD;
        const float* Vb = Vs + buf * 64 * VPAD;

        // S = Q K^T   (log2-scaled scores)
        float sc[8][4];
#pragma unroll
        for (int nt = 0; nt < 8; nt++)
#pragma unroll
            for (int c = 0; c < 4; c++) sc[nt][c] = 0.0f;
#pragma unroll
        for (int ks = 0; ks < 8; ks++) {
            int kc = ks * 8 + t4;
#pragma unroll
            for (int nt = 0; nt < 8; nt++) {
                int nn = nt * 8 + g;
                unsigned bfr[2];
                bfr[0] = tf32u(Kb[nn * KPAD + kc]);
                bfr[1] = tf32u(Kb[nn * KPAD + kc + 4]);
                mma_tf32(sc[nt], qf[ks], bfr);
            }
        }

        // causal mask (diagonal tile only)
        if (kt == qt) {
#pragma unroll
            for (int nt = 0; nt < 8; nt++) {
                int col = nt * 8 + t4 * 2;
#pragma unroll
                for (int c = 0; c < 4; c++) {
                    int cc = col + (c & 1);
                    int rr = qr + ((c >> 1) << 3);
                    if (cc > rr) sc[nt][c] = -1e30f;
                }
            }
        }

        // online softmax (base-2)
        float mt0 = -1e30f, mt1 = -1e30f;
#pragma unroll
        for (int nt = 0; nt < 8; nt++) {
            mt0 = fmaxf(mt0, fmaxf(sc[nt][0], sc[nt][1]));
            mt1 = fmaxf(mt1, fmaxf(sc[nt][2], sc[nt][3]));
        }
#pragma unroll
        for (int off = 1; off <= 2; off <<= 1) {
            mt0 = fmaxf(mt0, __shfl_xor_sync(0xffffffffu, mt0, off));
            mt1 = fmaxf(mt1, __shfl_xor_sync(0xffffffffu, mt1, off));
        }
        float mnew0 = fmaxf(mrow0, mt0), mnew1 = fmaxf(mrow1, mt1);
        float alpha0 = fast_exp2(mrow0 - mnew0), alpha1 = fast_exp2(mrow1 - mnew1);
        float lt0 = 0.0f, lt1 = 0.0f;
#pragma unroll
        for (int nt = 0; nt < 8; nt++) {
            sc[nt][0] = fast_exp2(sc[nt][0] - mnew0);
            sc[nt][1] = fast_exp2(sc[nt][1] - mnew0);
            sc[nt][2] = fast_exp2(sc[nt][2] - mnew1);
            sc[nt][3] = fast_exp2(sc[nt][3] - mnew1);
            lt0 += sc[nt][0] + sc[nt][1];
            lt1 += sc[nt][2] + sc[nt][3];
        }
#pragma unroll
        for (int off = 1; off <= 2; off <<= 1) {
            lt0 += __shfl_xor_sync(0xffffffffu, lt0, off);
            lt1 += __shfl_xor_sync(0xffffffffu, lt1, off);
        }
        mrow0 = mnew0; mrow1 = mnew1;
        lsum0 = lsum0 * alpha0 + lt0;
        lsum1 = lsum1 * alpha1 + lt1;
#pragma unroll
        for (int nt = 0; nt < 8; nt++) {
            o[nt][0] *= alpha0; o[nt][1] *= alpha0;
            o[nt][2] *= alpha1; o[nt][3] *= alpha1;
        }

        // P into this warp's private Q rows (tf32)
        float* Pw = Qs + (warp * 16) * KPAD;
#pragma unroll
        for (int nt = 0; nt < 8; nt++) {
            int col = nt * 8 + t4 * 2;
            Pw[g * KPAD + col]           = to_tf32(sc[nt][0]);
            Pw[g * KPAD + col + 1]       = to_tf32(sc[nt][1]);
            Pw[(g + 8) * KPAD + col]     = to_tf32(sc[nt][2]);
            Pw[(g + 8) * KPAD + col + 1] = to_tf32(sc[nt][3]);
        }
        __syncwarp();

        // O += P V
#pragma unroll
        for (int ks = 0; ks < 8; ks++) {
            int kc = ks * 8 + t4;
            unsigned pa[4];
            pa[0] = __float_as_uint(Pw[g * KPAD + kc]);
            pa[1] = __float_as_uint(Pw[(g + 8) * KPAD + kc]);
            pa[2] = __float_as_uint(Pw[g * KPAD + kc + 4]);
            pa[3] = __float_as_uint(Pw[(g + 8) * KPAD + kc + 4]);
#pragma unroll
            for (int nt = 0; nt < 8; nt++) {
                int nh = nt * 8 + g;
                unsigned vb[2];
                vb[0] = tf32u(Vb[kc * VPAD + nh]);
                vb[1] = tf32u(Vb[(kc + 4) * VPAD + nh]);
                mma_tf32(o[nt], pa, vb);
            }
        }
    }

    // Epilogue: store unnormalized partials + m, l
#pragma unroll
    for (int nt = 0; nt < 8; nt++) {
        int col = nt * 8 + t4 * 2;
        *(float2*)&opart[(size_t)qr * HS + col]       = make_float2(o[nt][0], o[nt][1]);
        *(float2*)&opart[(size_t)(qr + 8) * HS + col] = make_float2(o[nt][2], o[nt][3]);
    }
    if (t4 == 0) {
        mpart[qr]     = mrow0;  lpart[qr]     = lsum0;
        mpart[qr + 8] = mrow1;  lpart[qr + 8] = lsum1;
    }
}

// ---------------------------------------------------------------------------
// Kernel 3: combine the two splits.
// ---------------------------------------------------------------------------
__global__ __launch_bounds__(256) void combine_kernel(float* __restrict__ out)
{
    int i = blockIdx.x * blockDim.x + threadIdx.x;  // over MTOT*HS/4
    int row = i >> 4;
    int col = (i & 15) * 4;

    float m0 = g_mpart[row],        l0 = g_lpart[row];
    float m1 = g_mpart[MTOT + row], l1 = g_lpart[MTOT + row];
    float m  = fmaxf(m0, m1);
    float w0 = fast_exp2(m0 - m), w1 = fast_exp2(m1 - m);
    float inv = 1.0f / (l0 * w0 + l1 * w1);
    float s0 = w0 * inv, s1 = w1 * inv;

    float4 a = *(const float4*)&g_opart[(size_t)row * HS + col];
    float4 c = *(const float4*)&g_opart[(size_t)MTOT * HS + (size_t)row * HS + col];
    float4 r;
    r.x = a.x * s0 + c.x * s1;
    r.y = a.y * s0 + c.y * s1;
    r.z = a.z * s0 + c.z * s1;
    r.w = a.w * s0 + c.w * s1;
    *(float4*)&out[(size_t)row * HS + col] = r;
}

// ---------------------------------------------------------------------------
extern "C" void kernel_launch(void* const* d_in, const int* in_sizes, int n_in,
                              void* d_out, int out_size)
{
    const float* x  = (const float*)d_in[0];
    const float* Wq = (const float*)d_in[1];
    const float* bq = (const float*)d_in[2];
    const float* Wk = (const float*)d_in[3];
    const float* bk = (const float*)d_in[4];
    const float* Wv = (const float*)d_in[5];
    const float* bv = (const float*)d_in[6];
    float* out = (float*)d_out;

    cudaFuncSetAttribute(proj_kernel,
                         cudaFuncAttributeMaxDynamicSharedMemorySize, PROJ_SMEM);
    proj_kernel<<<MTOT / 64, 256, PROJ_SMEM>>>(x, Wq, bq, Wk, bk, Wv, bv);

    cudaFuncSetAttribute(attn_part_kernel,
                         cudaFuncAttributeMaxDynamicSharedMemorySize, ATTN_SMEM);
    dim3 gattn(NQT * 2, BATCH);
    attn_part_kernel<<<gattn, 128, ATTN_SMEM>>>();

    combine_kernel<<<(MTOT * HS / 4) / 256, 256>>>(out);
}

// round 7
// speedup vs baseline: 4.4541x; 1.1780x over previous
#include <cuda_runtime.h>
#include <cstdint>

#define BATCH 8
#define SEQ   2048
#define EMB   1024
#define HS    64
#define MTOT  (BATCH * SEQ)   // 16384
#define NQT   (SEQ / 64)      // 32 q-tiles per batch
#define QSCALE (0.125f * 1.44269504f)   // 1/sqrt(64) * log2(e)

// Scratch (tf32-rounded values, fragment-pair permuted layouts)
__device__ float g_wt[192 * EMB];          // [n][k_perm], q rows pre-scaled
__device__ float g_q[MTOT * HS];           // [token][h_perm], pre-scaled tf32
__device__ float g_k[MTOT * HS];           // [token][h_perm], tf32
__device__ float g_vt[MTOT * HS];          // [b][h][token_perm], tf32
__device__ float g_opart[2 * MTOT * HS];
__device__ float g_mpart[2 * MTOT];
__device__ float g_lpart[2 * MTOT];

__device__ __forceinline__ float to_tf32(float x) {
    float y;
    asm("cvt.rna.tf32.f32 %0, %1;" : "=f"(y) : "f"(x));
    return y;
}
__device__ __forceinline__ float fast_exp2(float x) {
    float y;
    asm("ex2.approx.ftz.f32 %0, %1;" : "=f"(y) : "f"(x));
    return y;
}
__device__ __forceinline__ void mma_tf32(float c[4], const unsigned a[4], const unsigned b[2]) {
    asm volatile(
        "mma.sync.aligned.m16n8k8.row.col.f32.tf32.tf32.f32 "
        "{%0,%1,%2,%3}, {%4,%5,%6,%7}, {%8,%9}, {%0,%1,%2,%3};"
        : "+f"(c[0]), "+f"(c[1]), "+f"(c[2]), "+f"(c[3])
        : "r"(a[0]), "r"(a[1]), "r"(a[2]), "r"(a[3]), "r"(b[0]), "r"(b[1]));
}
__device__ __forceinline__ void cp16(float* dst_smem, const float* src) {
    unsigned d = (unsigned)__cvta_generic_to_shared(dst_smem);
    asm volatile("cp.async.cg.shared.global [%0], [%1], 16;" :: "r"(d), "l"(src));
}
#define CP_COMMIT() asm volatile("cp.async.commit_group;")
#define CP_WAIT1()  asm volatile("cp.async.wait_group 1;")

// pair-permutation within an 8-group: k -> slot so (k, k+4) become adjacent
__device__ __host__ __forceinline__ int slotf(int o) { return ((o & 3) << 1) | (o >> 2); }

// ---------------------------------------------------------------------------
// Kernel 0: W pre-convert (tf32, permuted along k; q rows pre-scaled).
// grid = 192 blocks (one per n row), 256 threads.
// ---------------------------------------------------------------------------
__global__ __launch_bounds__(256) void wconv_kernel(
    const float* __restrict__ Wq, const float* __restrict__ Wk,
    const float* __restrict__ Wv)
{
    const int n = blockIdx.x;
    const float* src = (n < 64) ? Wq + (size_t)n * EMB
                     : (n < 128) ? Wk + (size_t)(n - 64) * EMB
                                 : Wv + (size_t)(n - 128) * EMB;
    const float s = (n < 64) ? QSCALE : 1.0f;
    const int k = threadIdx.x * 4;   // 256*4 = 1024 = EMB
    float4 v = *(const float4*)&src[k];
    const int gb = k & ~7;
    const int hb = (k & 4) ? 1 : 0;
    float* dst = g_wt + (size_t)n * EMB + gb;
    dst[0 * 2 + hb] = to_tf32(v.x * s);
    dst[1 * 2 + hb] = to_tf32(v.y * s);
    dst[2 * 2 + hb] = to_tf32(v.z * s);
    dst[3 * 2 + hb] = to_tf32(v.w * s);
}

// ---------------------------------------------------------------------------
// Kernel 1: fused QKV projection, tf32 MMA.
// W via cp.async from pre-converted g_wt; X via LDG->cvt->STS (reg prefetch).
// tile 64(M) x 192(N), BK=32. 256 threads = 8 warps (2M x 4N).
// ---------------------------------------------------------------------------
#define XST 40                      // smem stride (floats) for BK=32 tiles
#define PROJ_SMEM ((2 * 64 * XST + 2 * 192 * XST + 192) * 4)

__global__ __launch_bounds__(256) void proj_kernel(
    const float* __restrict__ x,
    const float* __restrict__ bq, const float* __restrict__ bk,
    const float* __restrict__ bv)
{
    extern __shared__ float sm[];
    float* Xs    = sm;                                 // [2][64][40]
    float* Wsm   = sm + 2 * 64 * XST;                  // [2][192][40]
    float* sbias = sm + 2 * 64 * XST + 2 * 192 * XST;  // [192]

    const int tid  = threadIdx.x;
    const int warp = tid >> 5;
    const int lane = tid & 31;
    const int g    = lane >> 2;
    const int t4   = lane & 3;
    const int mw   = warp >> 2;
    const int nw   = warp & 3;
    const int m0   = blockIdx.x * 64;

    if (tid < 192)
        sbias[tid] = (tid < 64) ? bq[tid] * QSCALE
                   : (tid < 128 ? bk[tid - 64] : bv[tid - 128]);

    // X load indices (2 float4 per thread per stage)
    const int xrow0 = tid >> 3;                 // 0..31  (i=0)
    const int xrow1 = (tid + 256) >> 3;         // 32..63 (i=1)
    const int xcol  = (tid & 7) * 4;            // 0..28
    const int xgb   = xcol & ~7;
    const int xhb   = (xcol & 4) ? 1 : 0;

    auto issueW = [&](int stage, int bs) {
        const int e0 = stage * 32;
        float* Wb = Wsm + bs * 192 * XST;
#pragma unroll
        for (int i = 0; i < 6; i++) {
            int id = tid + i * 256;
            int n = id >> 3, col = (id & 7) * 4;
            cp16(&Wb[n * XST + col], &g_wt[(size_t)n * EMB + e0 + col]);
        }
    };
    auto stsX = [&](const float4 xr[2], int bs) {
        float* Xb = Xs + bs * 64 * XST;
#pragma unroll
        for (int i = 0; i < 2; i++) {
            int row = i ? xrow1 : xrow0;
            float* d = &Xb[row * XST + xgb];
            d[0 * 2 + xhb] = to_tf32(xr[i].x);
            d[1 * 2 + xhb] = to_tf32(xr[i].y);
            d[2 * 2 + xhb] = to_tf32(xr[i].z);
            d[3 * 2 + xhb] = to_tf32(xr[i].w);
        }
    };

    float acc[2][6][4];
#pragma unroll
    for (int i = 0; i < 2; i++)
#pragma unroll
        for (int j = 0; j < 6; j++)
#pragma unroll
            for (int c = 0; c < 4; c++) acc[i][j][c] = 0.0f;

    float4 xr[2];
    xr[0] = *(const float4*)&x[(size_t)(m0 + xrow0) * EMB + xcol];
    xr[1] = *(const float4*)&x[(size_t)(m0 + xrow1) * EMB + xcol];
    issueW(0, 0);
    CP_COMMIT();

    const int NST = EMB / 32;
    for (int t = 0; t < NST; t++) {
        const int buf = t & 1;
        __syncthreads();                 // buffers free
        stsX(xr, buf);
        if (t + 1 < NST) {
            const int e0 = (t + 1) * 32;
            xr[0] = *(const float4*)&x[(size_t)(m0 + xrow0) * EMB + e0 + xcol];
            xr[1] = *(const float4*)&x[(size_t)(m0 + xrow1) * EMB + e0 + xcol];
            issueW(t + 1, buf ^ 1);
        }
        CP_COMMIT();
        CP_WAIT1();                      // W stage t resident
        __syncthreads();                 // X STS visible too

        const float* Xb = Xs + buf * 64 * XST;
        const float* Wb = Wsm + buf * 192 * XST;
#pragma unroll
        for (int ks = 0; ks < 4; ks++) {
            const int kc2 = ks * 8 + t4 * 2;
            unsigned a[2][4];
#pragma unroll
            for (int mt = 0; mt < 2; mt++) {
                int r = mw * 32 + mt * 16 + g;
                uint2 p0 = *(const uint2*)&Xb[r * XST + kc2];
                uint2 p1 = *(const uint2*)&Xb[(r + 8) * XST + kc2];
                a[mt][0] = p0.x; a[mt][2] = p0.y;
                a[mt][1] = p1.x; a[mt][3] = p1.y;
            }
#pragma unroll
            for (int nt = 0; nt < 6; nt++) {
                int n = nw * 48 + nt * 8 + g;
                uint2 wb2 = *(const uint2*)&Wb[n * XST + kc2];
                unsigned b[2] = {wb2.x, wb2.y};
                mma_tf32(acc[0][nt], a[0], b);
                mma_tf32(acc[1][nt], a[1], b);
            }
        }
    }

    // Epilogue: bias, tf32-round, scatter into permuted/transposed layouts
#pragma unroll
    for (int mt = 0; mt < 2; mt++) {
        const int r0 = m0 + mw * 32 + mt * 16 + g;     // global token
        const int bidx = r0 >> 11;                     // /SEQ
        const int tok  = r0 & (SEQ - 1);
        const int pt0 = (tok & ~7) | slotf(tok & 7);          // token perm (r0)
        const int pt1 = ((tok + 8) & ~7) | slotf(tok & 7);    // r0+8 (same in-group pos)
#pragma unroll
        for (int nt = 0; nt < 6; nt++) {
            const int ncol = nw * 48 + nt * 8 + t4 * 2;
            const float b0 = sbias[ncol], b1 = sbias[ncol + 1];
            const float v00 = to_tf32(acc[mt][nt][0] + b0);
            const float v01 = to_tf32(acc[mt][nt][1] + b1);
            const float v10 = to_tf32(acc[mt][nt][2] + b0);
            const float v11 = to_tf32(acc[mt][nt][3] + b1);
            if (ncol < 128) {
                float* dst = (ncol < 64) ? g_q : g_k;
                const int nl = ncol & 63;
                const int s0 = (nl & ~7) | slotf(nl & 7);
                const int s1 = ((nl + 1) & ~7) | slotf((nl + 1) & 7);
                dst[(size_t)r0 * HS + s0]       = v00;
                dst[(size_t)r0 * HS + s1]       = v01;
                dst[(size_t)(r0 + 8) * HS + s0] = v10;
                dst[(size_t)(r0 + 8) * HS + s1] = v11;
            } else {
                const int h = ncol - 128;
                float* base = g_vt + ((size_t)bidx * HS) * SEQ;
                base[(size_t)h * SEQ + pt0]       = v00;
                base[(size_t)(h + 1) * SEQ + pt0] = v01;
                base[(size_t)h * SEQ + pt1]       = v10;
                base[(size_t)(h + 1) * SEQ + pt1] = v11;
            }
        }
    }
}

// ---------------------------------------------------------------------------
// Kernel 2: causal flash attention partials, tf32 MMA, split-KV 2-way.
// All operands pre-rounded & pre-permuted -> zero cvt in mainloop, LDS.64 frags.
// 128 threads = 4 warps, BM=BN=64.
// ---------------------------------------------------------------------------
#define AST 72                       // smem stride (floats) for 64-wide tiles
#define ATTN_SMEM (5 * 64 * AST * 4)

__global__ __launch_bounds__(128) void attn_part_kernel()
{
    extern __shared__ float sm[];
    float* Qs = sm;                       // [64][72]; reused per-warp as P
    float* Ks = sm + 64 * AST;            // [2][64][72]  rows=token, cols=h_perm
    float* Vs = sm + 3 * 64 * AST;        // [2][64][72]  rows=h, cols=token_perm

    const int b  = blockIdx.y;
    const int bx = blockIdx.x;
    const int qt = NQT - 1 - (bx >> 1);
    const int s  = bx & 1;
    const int n  = qt + 1;
    const int h0 = (n + 1) >> 1;
    const int lo = s ? h0 : 0;
    const int hi = s ? n : h0;
    const int q0 = qt * 64;
    const int tid  = threadIdx.x;
    const int warp = tid >> 5;
    const int lane = tid & 31;
    const int g  = lane >> 2;
    const int t4 = lane & 3;

    float* opart = g_opart + ((size_t)s * MTOT + (size_t)b * SEQ + q0) * HS;
    float* mpart = g_mpart + s * MTOT + b * SEQ + q0;
    float* lpart = g_lpart + s * MTOT + b * SEQ + q0;

    if (lo >= hi) {
        for (int i = tid; i < 64 * HS; i += 128) opart[i] = 0.0f;
        if (tid < 64) { mpart[tid] = -1e30f; lpart[tid] = 0.0f; }
        return;
    }

    const float* qg = g_q + ((size_t)b * SEQ + q0) * HS;
    const float* kg = g_k + (size_t)b * SEQ * HS;
    const float* vtg = g_vt + (size_t)b * HS * SEQ;

    auto issue = [&](int kt, int bs) {
        float* Kb = Ks + bs * 64 * AST;
        float* Vb = Vs + bs * 64 * AST;
#pragma unroll
        for (int i = 0; i < 8; i++) {
            int id = tid + i * 128;
            int row = id >> 4, col = (id & 15) * 4;
            cp16(&Kb[row * AST + col], &kg[(size_t)(kt * 64 + row) * HS + col]);
            cp16(&Vb[row * AST + col], &vtg[(size_t)row * SEQ + kt * 64 + col]);
        }
    };

    // Stage Q (already scaled+rounded+permuted)
#pragma unroll
    for (int i = 0; i < 8; i++) {
        int id = tid + i * 128;
        int row = id >> 4, col = (id & 15) * 4;
        cp16(&Qs[row * AST + col], &qg[(size_t)row * HS + col]);
    }
    CP_COMMIT();
    issue(lo, 0);
    CP_COMMIT();
    CP_WAIT1();          // Q group done (KV(lo) may be in flight)
    __syncthreads();

    const int qr = warp * 16 + g;
    unsigned qf[8][4];
#pragma unroll
    for (int ks = 0; ks < 8; ks++) {
        const int kc2 = ks * 8 + t4 * 2;
        uint2 p0 = *(const uint2*)&Qs[qr * AST + kc2];
        uint2 p1 = *(const uint2*)&Qs[(qr + 8) * AST + kc2];
        qf[ks][0] = p0.x; qf[ks][2] = p0.y;
        qf[ks][1] = p1.x; qf[ks][3] = p1.y;
    }

    float o[8][4];
#pragma unroll
    for (int nt = 0; nt < 8; nt++)
#pragma unroll
        for (int c = 0; c < 4; c++) o[nt][c] = 0.0f;
    float mrow0 = -1e30f, mrow1 = -1e30f, lsum0 = 0.0f, lsum1 = 0.0f;

    for (int kt = lo; kt < hi; kt++) {
        const int buf = (kt - lo) & 1;
        __syncthreads();
        if (kt + 1 < hi) issue(kt + 1, buf ^ 1);
        CP_COMMIT();
        CP_WAIT1();
        __syncthreads();

        const float* Kb = Ks + buf * 64 * AST;
        const float* Vb = Vs + buf * 64 * AST;

        // S = Q K^T
        float sc[8][4];
#pragma unroll
        for (int nt = 0; nt < 8; nt++)
#pragma unroll
            for (int c = 0; c < 4; c++) sc[nt][c] = 0.0f;
#pragma unroll
        for (int ks = 0; ks < 8; ks++) {
            const int kc2 = ks * 8 + t4 * 2;
#pragma unroll
            for (int nt = 0; nt < 8; nt++) {
                uint2 kb2 = *(const uint2*)&Kb[(nt * 8 + g) * AST + kc2];
                unsigned bfr[2] = {kb2.x, kb2.y};
                mma_tf32(sc[nt], qf[ks], bfr);
            }
        }

        if (kt == qt) {   // causal mask, diagonal tile only
#pragma unroll
            for (int nt = 0; nt < 8; nt++) {
                int col = nt * 8 + t4 * 2;
#pragma unroll
                for (int c = 0; c < 4; c++) {
                    int cc = col + (c & 1);
                    int rr = qr + ((c >> 1) << 3);
                    if (cc > rr) sc[nt][c] = -1e30f;
                }
            }
        }

        // online softmax (base-2)
        float mt0 = -1e30f, mt1 = -1e30f;
#pragma unroll
        for (int nt = 0; nt < 8; nt++) {
            mt0 = fmaxf(mt0, fmaxf(sc[nt][0], sc[nt][1]));
            mt1 = fmaxf(mt1, fmaxf(sc[nt][2], sc[nt][3]));
        }
#pragma unroll
        for (int off = 1; off <= 2; off <<= 1) {
            mt0 = fmaxf(mt0, __shfl_xor_sync(0xffffffffu, mt0, off));
            mt1 = fmaxf(mt1, __shfl_xor_sync(0xffffffffu, mt1, off));
        }
        float mnew0 = fmaxf(mrow0, mt0), mnew1 = fmaxf(mrow1, mt1);
        float alpha0 = fast_exp2(mrow0 - mnew0), alpha1 = fast_exp2(mrow1 - mnew1);
        float lt0 = 0.0f, lt1 = 0.0f;
#pragma unroll
        for (int nt = 0; nt < 8; nt++) {
            sc[nt][0] = fast_exp2(sc[nt][0] - mnew0);
            sc[nt][1] = fast_exp2(sc[nt][1] - mnew0);
            sc[nt][2] = fast_exp2(sc[nt][2] - mnew1);
            sc[nt][3] = fast_exp2(sc[nt][3] - mnew1);
            lt0 += sc[nt][0] + sc[nt][1];
            lt1 += sc[nt][2] + sc[nt][3];
        }
#pragma unroll
        for (int off = 1; off <= 2; off <<= 1) {
            lt0 += __shfl_xor_sync(0xffffffffu, lt0, off);
            lt1 += __shfl_xor_sync(0xffffffffu, lt1, off);
        }
        mrow0 = mnew0; mrow1 = mnew1;
        lsum0 = lsum0 * alpha0 + lt0;
        lsum1 = lsum1 * alpha1 + lt1;
#pragma unroll
        for (int nt = 0; nt < 8; nt++) {
            o[nt][0] *= alpha0; o[nt][1] *= alpha0;
            o[nt][2] *= alpha1; o[nt][3] *= alpha1;
        }

        // P into this warp's private Q rows (tf32, token-permuted cols)
        float* Pw = Qs + (warp * 16) * AST;
        {
            const int o0 = t4 * 2, o1 = o0 + 1;
            const int s0 = slotf(o0), s1 = slotf(o1);
#pragma unroll
            for (int nt = 0; nt < 8; nt++) {
                const int cb = nt * 8;
                Pw[g * AST + cb + s0]       = to_tf32(sc[nt][0]);
                Pw[g * AST + cb + s1]       = to_tf32(sc[nt][1]);
                Pw[(g + 8) * AST + cb + s0] = to_tf32(sc[nt][2]);
                Pw[(g + 8) * AST + cb + s1] = to_tf32(sc[nt][3]);
            }
        }
        __syncwarp();

        // O += P V
#pragma unroll
        for (int ks = 0; ks < 8; ks++) {
            const int kc2 = ks * 8 + t4 * 2;
            uint2 p0 = *(const uint2*)&Pw[g * AST + kc2];
            uint2 p1 = *(const uint2*)&Pw[(g + 8) * AST + kc2];
            unsigned pa[4] = {p0.x, p1.x, p0.y, p1.y};
#pragma unroll
            for (int nt = 0; nt < 8; nt++) {
                uint2 vv = *(const uint2*)&Vb[(nt * 8 + g) * AST + kc2];
                unsigned vb2[2] = {vv.x, vv.y};
                mma_tf32(o[nt], pa, vb2);
            }
        }
    }

    // Epilogue (h-dim of O is unpermuted)
#pragma unroll
    for (int nt = 0; nt < 8; nt++) {
        int col = nt * 8 + t4 * 2;
        *(float2*)&opart[(size_t)qr * HS + col]       = make_float2(o[nt][0], o[nt][1]);
        *(float2*)&opart[(size_t)(qr + 8) * HS + col] = make_float2(o[nt][2], o[nt][3]);
    }
    if (t4 == 0) {
        mpart[qr]     = mrow0;  lpart[qr]     = lsum0;
        mpart[qr + 8] = mrow1;  lpart[qr + 8] = lsum1;
    }
}

// ---------------------------------------------------------------------------
// Kernel 3: combine the two splits.
// ---------------------------------------------------------------------------
__global__ __launch_bounds__(256) void combine_kernel(float* __restrict__ out)
{
    int i = blockIdx.x * blockDim.x + threadIdx.x;
    int row = i >> 4;
    int col = (i & 15) * 4;

    float m0 = g_mpart[row],        l0 = g_lpart[row];
    float m1 = g_mpart[MTOT + row], l1 = g_lpart[MTOT + row];
    float m  = fmaxf(m0, m1);
    float w0 = fast_exp2(m0 - m), w1 = fast_exp2(m1 - m);
    float inv = 1.0f / (l0 * w0 + l1 * w1);
    float s0 = w0 * inv, s1 = w1 * inv;

    float4 a = *(const float4*)&g_opart[(size_t)row * HS + col];
    float4 c = *(const float4*)&g_opart[(size_t)MTOT * HS + (size_t)row * HS + col];
    float4 r;
    r.x = a.x * s0 + c.x * s1;
    r.y = a.y * s0 + c.y * s1;
    r.z = a.z * s0 + c.z * s1;
    r.w = a.w * s0 + c.w * s1;
    *(float4*)&out[(size_t)row * HS + col] = r;
}

// ---------------------------------------------------------------------------
extern "C" void kernel_launch(void* const* d_in, const int* in_sizes, int n_in,
                              void* d_out, int out_size)
{
    const float* x  = (const float*)d_in[0];
    const float* Wq = (const float*)d_in[1];
    const float* bq = (const float*)d_in[2];
    const float* Wk = (const float*)d_in[3];
    const float* bk = (const float*)d_in[4];
    const float* Wv = (const float*)d_in[5];
    const float* bv = (const float*)d_in[6];
    float* out = (float*)d_out;

    wconv_kernel<<<192, 256>>>(Wq, Wk, Wv);

    cudaFuncSetAttribute(proj_kernel,
                         cudaFuncAttributeMaxDynamicSharedMemorySize, PROJ_SMEM);
    proj_kernel<<<MTOT / 64, 256, PROJ_SMEM>>>(x, bq, bk, bv);

    cudaFuncSetAttribute(attn_part_kernel,
                         cudaFuncAttributeMaxDynamicSharedMemorySize, ATTN_SMEM);
    dim3 gattn(NQT * 2, BATCH);
    attn_part_kernel<<<gattn, 128, ATTN_SMEM>>>();

    combine_kernel<<<(MTOT * HS / 4) / 256, 256>>>(out);
}

// round 8
// speedup vs baseline: 4.5792x; 1.0281x over previous
#include <cuda_runtime.h>
#include <cstdint>

#define BATCH 8
#define SEQ   2048
#define EMB   1024
#define HS    64
#define MTOT  (BATCH * SEQ)   // 16384
#define NQT   (SEQ / 64)      // 32 q-tiles per batch
#define NSPLIT 4
#define QSCALE (0.125f * 1.44269504f)   // 1/sqrt(64) * log2(e)

// Scratch (tf32-rounded values, fragment-pair permuted layouts)
__device__ float g_wt[192 * EMB];          // [n][k_perm], q rows pre-scaled
__device__ float g_q[MTOT * HS];           // [token][h_perm], pre-scaled tf32
__device__ float g_k[MTOT * HS];           // [token][h_perm], tf32
__device__ float g_vt[MTOT * HS];          // [b][h][token_perm], tf32
__device__ float g_opart[NSPLIT * MTOT * HS];
__device__ float g_mpart[NSPLIT * MTOT];
__device__ float g_lpart[NSPLIT * MTOT];

__device__ __forceinline__ float to_tf32(float x) {
    float y;
    asm("cvt.rna.tf32.f32 %0, %1;" : "=f"(y) : "f"(x));
    return y;
}
__device__ __forceinline__ float fast_exp2(float x) {
    float y;
    asm("ex2.approx.ftz.f32 %0, %1;" : "=f"(y) : "f"(x));
    return y;
}
__device__ __forceinline__ void mma_tf32(float c[4], const unsigned a[4], const unsigned b[2]) {
    asm volatile(
        "mma.sync.aligned.m16n8k8.row.col.f32.tf32.tf32.f32 "
        "{%0,%1,%2,%3}, {%4,%5,%6,%7}, {%8,%9}, {%0,%1,%2,%3};"
        : "+f"(c[0]), "+f"(c[1]), "+f"(c[2]), "+f"(c[3])
        : "r"(a[0]), "r"(a[1]), "r"(a[2]), "r"(a[3]), "r"(b[0]), "r"(b[1]));
}
__device__ __forceinline__ void cp16(float* dst_smem, const float* src) {
    unsigned d = (unsigned)__cvta_generic_to_shared(dst_smem);
    asm volatile("cp.async.cg.shared.global [%0], [%1], 16;" :: "r"(d), "l"(src));
}
#define CP_COMMIT() asm volatile("cp.async.commit_group;")
#define CP_WAIT0()  asm volatile("cp.async.wait_group 0;")
#define CP_WAIT1()  asm volatile("cp.async.wait_group 1;")

// pair-permutation within an 8-group: k -> slot so (k, k+4) become adjacent
__device__ __host__ __forceinline__ int slotf(int o) { return ((o & 3) << 1) | (o >> 2); }

// ---------------------------------------------------------------------------
// Kernel 0: W pre-convert (tf32, permuted along k; q rows pre-scaled).
// ---------------------------------------------------------------------------
__global__ __launch_bounds__(256) void wconv_kernel(
    const float* __restrict__ Wq, const float* __restrict__ Wk,
    const float* __restrict__ Wv)
{
    const int n = blockIdx.x;
    const float* src = (n < 64) ? Wq + (size_t)n * EMB
                     : (n < 128) ? Wk + (size_t)(n - 64) * EMB
                                 : Wv + (size_t)(n - 128) * EMB;
    const float s = (n < 64) ? QSCALE : 1.0f;
    const int k = threadIdx.x * 4;
    float4 v = *(const float4*)&src[k];
    const int gb = k & ~7;
    const int hb = (k & 4) ? 1 : 0;
    float* dst = g_wt + (size_t)n * EMB + gb;
    dst[0 * 2 + hb] = to_tf32(v.x * s);
    dst[1 * 2 + hb] = to_tf32(v.y * s);
    dst[2 * 2 + hb] = to_tf32(v.z * s);
    dst[3 * 2 + hb] = to_tf32(v.w * s);
}

// ---------------------------------------------------------------------------
// Kernel 1: fused QKV projection, tf32 MMA (unchanged from round 7).
// ---------------------------------------------------------------------------
#define XST 40
#define PROJ_SMEM ((2 * 64 * XST + 2 * 192 * XST + 192) * 4)

__global__ __launch_bounds__(256) void proj_kernel(
    const float* __restrict__ x,
    const float* __restrict__ bq, const float* __restrict__ bk,
    const float* __restrict__ bv)
{
    extern __shared__ float sm[];
    float* Xs    = sm;
    float* Wsm   = sm + 2 * 64 * XST;
    float* sbias = sm + 2 * 64 * XST + 2 * 192 * XST;

    const int tid  = threadIdx.x;
    const int warp = tid >> 5;
    const int lane = tid & 31;
    const int g    = lane >> 2;
    const int t4   = lane & 3;
    const int mw   = warp >> 2;
    const int nw   = warp & 3;
    const int m0   = blockIdx.x * 64;

    if (tid < 192)
        sbias[tid] = (tid < 64) ? bq[tid] * QSCALE
                   : (tid < 128 ? bk[tid - 64] : bv[tid - 128]);

    const int xrow0 = tid >> 3;
    const int xrow1 = (tid + 256) >> 3;
    const int xcol  = (tid & 7) * 4;
    const int xgb   = xcol & ~7;
    const int xhb   = (xcol & 4) ? 1 : 0;

    auto issueW = [&](int stage, int bs) {
        const int e0 = stage * 32;
        float* Wb = Wsm + bs * 192 * XST;
#pragma unroll
        for (int i = 0; i < 6; i++) {
            int id = tid + i * 256;
            int n = id >> 3, col = (id & 7) * 4;
            cp16(&Wb[n * XST + col], &g_wt[(size_t)n * EMB + e0 + col]);
        }
    };
    auto stsX = [&](const float4 xr[2], int bs) {
        float* Xb = Xs + bs * 64 * XST;
#pragma unroll
        for (int i = 0; i < 2; i++) {
            int row = i ? xrow1 : xrow0;
            float* d = &Xb[row * XST + xgb];
            d[0 * 2 + xhb] = to_tf32(xr[i].x);
            d[1 * 2 + xhb] = to_tf32(xr[i].y);
            d[2 * 2 + xhb] = to_tf32(xr[i].z);
            d[3 * 2 + xhb] = to_tf32(xr[i].w);
        }
    };

    float acc[2][6][4];
#pragma unroll
    for (int i = 0; i < 2; i++)
#pragma unroll
        for (int j = 0; j < 6; j++)
#pragma unroll
            for (int c = 0; c < 4; c++) acc[i][j][c] = 0.0f;

    float4 xr[2];
    xr[0] = *(const float4*)&x[(size_t)(m0 + xrow0) * EMB + xcol];
    xr[1] = *(const float4*)&x[(size_t)(m0 + xrow1) * EMB + xcol];
    issueW(0, 0);
    CP_COMMIT();

    const int NST = EMB / 32;
    for (int t = 0; t < NST; t++) {
        const int buf = t & 1;
        __syncthreads();
        stsX(xr, buf);
        if (t + 1 < NST) {
            const int e0 = (t + 1) * 32;
            xr[0] = *(const float4*)&x[(size_t)(m0 + xrow0) * EMB + e0 + xcol];
            xr[1] = *(const float4*)&x[(size_t)(m0 + xrow1) * EMB + e0 + xcol];
            issueW(t + 1, buf ^ 1);
        }
        CP_COMMIT();
        CP_WAIT1();
        __syncthreads();

        const float* Xb = Xs + buf * 64 * XST;
        const float* Wb = Wsm + buf * 192 * XST;
#pragma unroll
        for (int ks = 0; ks < 4; ks++) {
            const int kc2 = ks * 8 + t4 * 2;
            unsigned a[2][4];
#pragma unroll
            for (int mt = 0; mt < 2; mt++) {
                int r = mw * 32 + mt * 16 + g;
                uint2 p0 = *(const uint2*)&Xb[r * XST + kc2];
                uint2 p1 = *(const uint2*)&Xb[(r + 8) * XST + kc2];
                a[mt][0] = p0.x; a[mt][2] = p0.y;
                a[mt][1] = p1.x; a[mt][3] = p1.y;
            }
#pragma unroll
            for (int nt = 0; nt < 6; nt++) {
                int n = nw * 48 + nt * 8 + g;
                uint2 wb2 = *(const uint2*)&Wb[n * XST + kc2];
                unsigned b[2] = {wb2.x, wb2.y};
                mma_tf32(acc[0][nt], a[0], b);
                mma_tf32(acc[1][nt], a[1], b);
            }
        }
    }

#pragma unroll
    for (int mt = 0; mt < 2; mt++) {
        const int r0 = m0 + mw * 32 + mt * 16 + g;
        const int bidx = r0 >> 11;
        const int tok  = r0 & (SEQ - 1);
        const int pt0 = (tok & ~7) | slotf(tok & 7);
        const int pt1 = ((tok + 8) & ~7) | slotf(tok & 7);
#pragma unroll
        for (int nt = 0; nt < 6; nt++) {
            const int ncol = nw * 48 + nt * 8 + t4 * 2;
            const float b0 = sbias[ncol], b1 = sbias[ncol + 1];
            const float v00 = to_tf32(acc[mt][nt][0] + b0);
            const float v01 = to_tf32(acc[mt][nt][1] + b1);
            const float v10 = to_tf32(acc[mt][nt][2] + b0);
            const float v11 = to_tf32(acc[mt][nt][3] + b1);
            if (ncol < 128) {
                float* dst = (ncol < 64) ? g_q : g_k;
                const int nl = ncol & 63;
                const int s0 = (nl & ~7) | slotf(nl & 7);
                const int s1 = ((nl + 1) & ~7) | slotf((nl + 1) & 7);
                dst[(size_t)r0 * HS + s0]       = v00;
                dst[(size_t)r0 * HS + s1]       = v01;
                dst[(size_t)(r0 + 8) * HS + s0] = v10;
                dst[(size_t)(r0 + 8) * HS + s1] = v11;
            } else {
                const int h = ncol - 128;
                float* base = g_vt + ((size_t)bidx * HS) * SEQ;
                base[(size_t)h * SEQ + pt0]       = v00;
                base[(size_t)(h + 1) * SEQ + pt0] = v01;
                base[(size_t)h * SEQ + pt1]       = v10;
                base[(size_t)(h + 1) * SEQ + pt1] = v11;
            }
        }
    }
}

// ---------------------------------------------------------------------------
// Kernel 2: causal flash attention partials, tf32 MMA, split-KV 4-way.
// Smem: P/Q slab + K double buffer + V single buffer = 4 slabs = 72KB
// -> 3 CTAs/SM. V(kt) load hidden behind S-MMA + softmax of iter kt.
// ---------------------------------------------------------------------------
#define AST 72
#define ATTN_SMEM (4 * 64 * AST * 4)

__global__ __launch_bounds__(128, 3) void attn_part_kernel()
{
    extern __shared__ float sm[];
    float* Qs = sm;                       // [64][72]; reused per-warp as P
    float* Ks = sm + 64 * AST;            // [2][64][72] rows=token, cols=h_perm
    float* Vs = sm + 3 * 64 * AST;        // [64][72]    rows=h, cols=token_perm

    const int b  = blockIdx.y;
    const int bx = blockIdx.x;
    const int qt = NQT - 1 - (bx >> 2);   // large tiles first
    const int s  = bx & 3;
    const int n  = qt + 1;
    const int c  = (n + 3) >> 2;
    const int lo = min(n, s * c);
    const int hi = min(n, lo + c);
    const int q0 = qt * 64;
    const int tid  = threadIdx.x;
    const int warp = tid >> 5;
    const int lane = tid & 31;
    const int g  = lane >> 2;
    const int t4 = lane & 3;

    float* opart = g_opart + ((size_t)s * MTOT + (size_t)b * SEQ + q0) * HS;
    float* mpart = g_mpart + s * MTOT + b * SEQ + q0;
    float* lpart = g_lpart + s * MTOT + b * SEQ + q0;

    if (lo >= hi) {   // empty split: weight becomes exactly 0 in combine
        if (tid < 64) { mpart[tid] = -1e30f; lpart[tid] = 0.0f; }
        return;
    }

    const float* qg  = g_q + ((size_t)b * SEQ + q0) * HS;
    const float* kg  = g_k + (size_t)b * SEQ * HS;
    const float* vtg = g_vt + (size_t)b * HS * SEQ;

    auto issueK = [&](int kt, int bs) {
        float* Kb = Ks + bs * 64 * AST;
#pragma unroll
        for (int i = 0; i < 8; i++) {
            int id = tid + i * 128;
            int row = id >> 4, col = (id & 15) * 4;
            cp16(&Kb[row * AST + col], &kg[(size_t)(kt * 64 + row) * HS + col]);
        }
    };
    auto issueV = [&](int kt) {
#pragma unroll
        for (int i = 0; i < 8; i++) {
            int id = tid + i * 128;
            int row = id >> 4, col = (id & 15) * 4;
            cp16(&Vs[row * AST + col], &vtg[(size_t)row * SEQ + kt * 64 + col]);
        }
    };

    // Prologue: stage Q and K(lo)
#pragma unroll
    for (int i = 0; i < 8; i++) {
        int id = tid + i * 128;
        int row = id >> 4, col = (id & 15) * 4;
        cp16(&Qs[row * AST + col], &qg[(size_t)row * HS + col]);
    }
    CP_COMMIT();
    issueK(lo, 0);
    CP_COMMIT();
    CP_WAIT0();
    __syncthreads();

    const int qr = warp * 16 + g;
    unsigned qf[8][4];
#pragma unroll
    for (int ks = 0; ks < 8; ks++) {
        const int kc2 = ks * 8 + t4 * 2;
        uint2 p0 = *(const uint2*)&Qs[qr * AST + kc2];
        uint2 p1 = *(const uint2*)&Qs[(qr + 8) * AST + kc2];
        qf[ks][0] = p0.x; qf[ks][2] = p0.y;
        qf[ks][1] = p1.x; qf[ks][3] = p1.y;
    }

    float o[8][4];
#pragma unroll
    for (int nt = 0; nt < 8; nt++)
#pragma unroll
        for (int cc = 0; cc < 4; cc++) o[nt][cc] = 0.0f;
    float mrow0 = -1e30f, mrow1 = -1e30f, lsum0 = 0.0f, lsum1 = 0.0f;

    for (int kt = lo; kt < hi; kt++) {
        const int kb = (kt - lo) & 1;
        if (kt > lo) CP_WAIT0();   // K(kt) resident
        __syncthreads();           // prev PV done: V/P slabs safe to overwrite

        issueV(kt);                // group B: V(kt), needed after S+softmax
        CP_COMMIT();
        if (kt + 1 < hi) issueK(kt + 1, kb ^ 1);
        CP_COMMIT();               // group A (possibly empty)

        const float* Kb = Ks + kb * 64 * AST;

        // S = Q K^T
        float sc[8][4];
#pragma unroll
        for (int nt = 0; nt < 8; nt++)
#pragma unroll
            for (int cc = 0; cc < 4; cc++) sc[nt][cc] = 0.0f;
#pragma unroll
        for (int ks = 0; ks < 8; ks++) {
            const int kc2 = ks * 8 + t4 * 2;
#pragma unroll
            for (int nt = 0; nt < 8; nt++) {
                uint2 kb2 = *(const uint2*)&Kb[(nt * 8 + g) * AST + kc2];
                unsigned bfr[2] = {kb2.x, kb2.y};
                mma_tf32(sc[nt], qf[ks], bfr);
            }
        }

        if (kt == qt) {   // causal mask, diagonal tile only
#pragma unroll
            for (int nt = 0; nt < 8; nt++) {
                int col = nt * 8 + t4 * 2;
#pragma unroll
                for (int cc = 0; cc < 4; cc++) {
                    int ccol = col + (cc & 1);
                    int rr = qr + ((cc >> 1) << 3);
                    if (ccol > rr) sc[nt][cc] = -1e30f;
                }
            }
        }

        // online softmax (base-2)
        float mt0 = -1e30f, mt1 = -1e30f;
#pragma unroll
        for (int nt = 0; nt < 8; nt++) {
            mt0 = fmaxf(mt0, fmaxf(sc[nt][0], sc[nt][1]));
            mt1 = fmaxf(mt1, fmaxf(sc[nt][2], sc[nt][3]));
        }
#pragma unroll
        for (int off = 1; off <= 2; off <<= 1) {
            mt0 = fmaxf(mt0, __shfl_xor_sync(0xffffffffu, mt0, off));
            mt1 = fmaxf(mt1, __shfl_xor_sync(0xffffffffu, mt1, off));
        }
        float mnew0 = fmaxf(mrow0, mt0), mnew1 = fmaxf(mrow1, mt1);
        float alpha0 = fast_exp2(mrow0 - mnew0), alpha1 = fast_exp2(mrow1 - mnew1);
        float lt0 = 0.0f, lt1 = 0.0f;
#pragma unroll
        for (int nt = 0; nt < 8; nt++) {
            sc[nt][0] = fast_exp2(sc[nt][0] - mnew0);
            sc[nt][1] = fast_exp2(sc[nt][1] - mnew0);
            sc[nt][2] = fast_exp2(sc[nt][2] - mnew1);
            sc[nt][3] = fast_exp2(sc[nt][3] - mnew1);
            lt0 += sc[nt][0] + sc[nt][1];
            lt1 += sc[nt][2] + sc[nt][3];
        }
#pragma unroll
        for (int off = 1; off <= 2; off <<= 1) {
            lt0 += __shfl_xor_sync(0xffffffffu, lt0, off);
            lt1 += __shfl_xor_sync(0xffffffffu, lt1, off);
        }
        mrow0 = mnew0; mrow1 = mnew1;
        lsum0 = lsum0 * alpha0 + lt0;
        lsum1 = lsum1 * alpha1 + lt1;
#pragma unroll
        for (int nt = 0; nt < 8; nt++) {
            o[nt][0] *= alpha0; o[nt][1] *= alpha0;
            o[nt][2] *= alpha1; o[nt][3] *= alpha1;
        }

        // P into this warp's private Q rows (tf32, token-permuted cols)
        float* Pw = Qs + (warp * 16) * AST;
        {
            const int o0 = t4 * 2, o1 = o0 + 1;
            const int s0 = slotf(o0), s1 = slotf(o1);
#pragma unroll
            for (int nt = 0; nt < 8; nt++) {
                const int cb = nt * 8;
                Pw[g * AST + cb + s0]       = to_tf32(sc[nt][0]);
                Pw[g * AST + cb + s1]       = to_tf32(sc[nt][1]);
                Pw[(g + 8) * AST + cb + s0] = to_tf32(sc[nt][2]);
                Pw[(g + 8) * AST + cb + s1] = to_tf32(sc[nt][3]);
            }
        }
        __syncwarp();

        CP_WAIT1();        // V(kt) resident (K(kt+1) may still be in flight)
        __syncthreads();   // all threads' V copies visible

        // O += P V
#pragma unroll
        for (int ks = 0; ks < 8; ks++) {
            const int kc2 = ks * 8 + t4 * 2;
            uint2 p0 = *(const uint2*)&Pw[g * AST + kc2];
            uint2 p1 = *(const uint2*)&Pw[(g + 8) * AST + kc2];
            unsigned pa[4] = {p0.x, p1.x, p0.y, p1.y};
#pragma unroll
            for (int nt = 0; nt < 8; nt++) {
                uint2 vv = *(const uint2*)&Vs[(nt * 8 + g) * AST + kc2];
                unsigned vb2[2] = {vv.x, vv.y};
                mma_tf32(o[nt], pa, vb2);
            }
        }
    }

    // Epilogue
#pragma unroll
    for (int nt = 0; nt < 8; nt++) {
        int col = nt * 8 + t4 * 2;
        *(float2*)&opart[(size_t)qr * HS + col]       = make_float2(o[nt][0], o[nt][1]);
        *(float2*)&opart[(size_t)(qr + 8) * HS + col] = make_float2(o[nt][2], o[nt][3]);
    }
    if (t4 == 0) {
        mpart[qr]     = mrow0;  lpart[qr]     = lsum0;
        mpart[qr + 8] = mrow1;  lpart[qr + 8] = lsum1;
    }
}

// ---------------------------------------------------------------------------
// Kernel 3: combine the four splits.
// ---------------------------------------------------------------------------
__global__ __launch_bounds__(256) void combine_kernel(float* __restrict__ out)
{
    int i = blockIdx.x * blockDim.x + threadIdx.x;
    int row = i >> 4;
    int col = (i & 15) * 4;

    float ms[NSPLIT], ls[NSPLIT];
    float m = -1e30f;
#pragma unroll
    for (int s = 0; s < NSPLIT; s++) {
        ms[s] = g_mpart[s * MTOT + row];
        ls[s] = g_lpart[s * MTOT + row];
        m = fmaxf(m, ms[s]);
    }
    float w[NSPLIT], L = 0.0f;
#pragma unroll
    for (int s = 0; s < NSPLIT; s++) {
        w[s] = fast_exp2(ms[s] - m);
        L += ls[s] * w[s];
    }
    float inv = 1.0f / L;

    float4 r = make_float4(0.f, 0.f, 0.f, 0.f);
#pragma unroll
    for (int s = 0; s < NSPLIT; s++) {
        if (ls[s] > 0.0f) {
            float sw = w[s] * inv;
            float4 a = *(const float4*)&g_opart[((size_t)s * MTOT + row) * HS + col];
            r.x += a.x * sw; r.y += a.y * sw;
            r.z += a.z * sw; r.w += a.w * sw;
        }
    }
    *(float4*)&out[(size_t)row * HS + col] = r;
}

// ---------------------------------------------------------------------------
extern "C" void kernel_launch(void* const* d_in, const int* in_sizes, int n_in,
                              void* d_out, int out_size)
{
    const float* x  = (const float*)d_in[0];
    const float* Wq = (const float*)d_in[1];
    const float* bq = (const float*)d_in[2];
    const float* Wk = (const float*)d_in[3];
    const float* bk = (const float*)d_in[4];
    const float* Wv = (const float*)d_in[5];
    const float* bv = (const float*)d_in[6];
    float* out = (float*)d_out;

    wconv_kernel<<<192, 256>>>(Wq, Wk, Wv);

    cudaFuncSetAttribute(proj_kernel,
                         cudaFuncAttributeMaxDynamicSharedMemorySize, PROJ_SMEM);
    proj_kernel<<<MTOT / 64, 256, PROJ_SMEM>>>(x, bq, bk, bv);

    cudaFuncSetAttribute(attn_part_kernel,
                         cudaFuncAttributeMaxDynamicSharedMemorySize, ATTN_SMEM);
    dim3 gattn(NQT * NSPLIT, BATCH);
    attn_part_kernel<<<gattn, 128, ATTN_SMEM>>>();

    combine_kernel<<<(MTOT * HS / 4) / 256, 256>>>(out);
}

// round 9
// speedup vs baseline: 7.0911x; 1.5485x over previous
#include <cuda_runtime.h>
#include <cuda_fp16.h>
#include <cstdint>

#define BATCH 8
#define SEQ   2048
#define EMB   1024
#define HS    64
#define MTOT  (BATCH * SEQ)   // 16384
#define NQT   (SEQ / 64)      // 32 q-tiles per batch
#define NSPLIT 4
#define QSCALE (0.125f * 1.44269504f)   // 1/sqrt(64) * log2(e)

// Scratch: fp16 operands in fragment-pair-permuted (16-group) layouts
__device__ __half g_wt[192 * EMB];         // [n][k_perm16], q rows pre-scaled
__device__ __half g_q[MTOT * HS];          // [token][h_perm16], pre-scaled
__device__ __half g_k[MTOT * HS];          // [token][h_perm16]
__device__ __half g_vt[MTOT * HS];         // [b][h][token_perm16]
__device__ float g_opart[NSPLIT * MTOT * HS];
__device__ float g_mpart[NSPLIT * MTOT];
__device__ float g_lpart[NSPLIT * MTOT];

__device__ __forceinline__ float fast_exp2(float x) {
    float y;
    asm("ex2.approx.ftz.f32 %0, %1;" : "=f"(y) : "f"(x));
    return y;
}
__device__ __forceinline__ void mma_f16(float c[4], const unsigned a[4], const unsigned b[2]) {
    asm volatile(
        "mma.sync.aligned.m16n8k16.row.col.f32.f16.f16.f32 "
        "{%0,%1,%2,%3}, {%4,%5,%6,%7}, {%8,%9}, {%0,%1,%2,%3};"
        : "+f"(c[0]), "+f"(c[1]), "+f"(c[2]), "+f"(c[3])
        : "r"(a[0]), "r"(a[1]), "r"(a[2]), "r"(a[3]), "r"(b[0]), "r"(b[1]));
}
__device__ __forceinline__ void cp16(void* dst_smem, const void* src) {
    unsigned d = (unsigned)__cvta_generic_to_shared(dst_smem);
    asm volatile("cp.async.cg.shared.global [%0], [%1], 16;" :: "r"(d), "l"(src));
}
#define CP_COMMIT() asm volatile("cp.async.commit_group;")
#define CP_WAIT0()  asm volatile("cp.async.wait_group 0;")
#define CP_WAIT1()  asm volatile("cp.async.wait_group 1;")

// perm16: within a 16-group, source offsets {2p,2p+1,2p+8,2p+9} -> {4p..4p+3}
// float4 at 4-aligned offset o (o&15 = 4*hq): halves (x,y) -> pos pa, (z,w) -> pa+4
__device__ __forceinline__ int posA4(int hq) { return ((hq & 1) << 3) | ((hq >> 1) << 1); }

// ---------------------------------------------------------------------------
// Kernel 0: W pre-convert to fp16 perm16 (q rows pre-scaled).
// ---------------------------------------------------------------------------
__global__ __launch_bounds__(256) void wconv_kernel(
    const float* __restrict__ Wq, const float* __restrict__ Wk,
    const float* __restrict__ Wv)
{
    const int n = blockIdx.x;
    const float* src = (n < 64) ? Wq + (size_t)n * EMB
                     : (n < 128) ? Wk + (size_t)(n - 64) * EMB
                                 : Wv + (size_t)(n - 128) * EMB;
    const float s = (n < 64) ? QSCALE : 1.0f;
    const int k = threadIdx.x * 4;
    float4 v = *(const float4*)&src[k];
    const int grp = k & ~15;
    const int pa  = posA4((k & 15) >> 2);
    __half* dst = g_wt + (size_t)n * EMB + grp;
    *(__half2*)&dst[pa]     = __floats2half2_rn(v.x * s, v.y * s);
    *(__half2*)&dst[pa + 4] = __floats2half2_rn(v.z * s, v.w * s);
}

// ---------------------------------------------------------------------------
// Kernel 1: fused QKV projection, fp16 MMA (m16n8k16), fp32 accumulate.
// tile 64(M) x 192(N), BK=32. 256 threads = 8 warps (2M x 4N).
// Smem strides: 48 halves per 32-half row (conflict-free).
// ---------------------------------------------------------------------------
#define XST 48   // halves per row (BK=32 data + pad)
#define PROJ_SMEM ((2 * 64 * XST + 2 * 192 * XST) * 2 + 192 * 4)

__global__ __launch_bounds__(256) void proj_kernel(
    const float* __restrict__ x,
    const float* __restrict__ bq, const float* __restrict__ bk,
    const float* __restrict__ bv)
{
    extern __shared__ char smraw[];
    __half* Xs    = (__half*)smraw;                         // [2][64][48]
    __half* Wsm   = Xs + 2 * 64 * XST;                      // [2][192][48]
    float*  sbias = (float*)(Wsm + 2 * 192 * XST);          // [192]

    const int tid  = threadIdx.x;
    const int warp = tid >> 5;
    const int lane = tid & 31;
    const int g    = lane >> 2;
    const int t4   = lane & 3;
    const int mw   = warp >> 2;
    const int nw   = warp & 3;
    const int m0   = blockIdx.x * 64;

    if (tid < 192)
        sbias[tid] = (tid < 64) ? bq[tid] * QSCALE
                   : (tid < 128 ? bk[tid - 64] : bv[tid - 128]);

    // X: 2 float4 loads per thread per stage
    const int xrow0 = tid >> 3;
    const int xrow1 = (tid + 256) >> 3;
    const int xcol  = (tid & 7) * 4;                 // 0..28
    const int xgrp  = xcol & ~15;
    const int xpa   = posA4((xcol & 15) >> 2);

    auto issueW = [&](int stage, int bs) {
        const int e0 = stage * 32;
        __half* Wb = Wsm + bs * 192 * XST;
#pragma unroll
        for (int i = 0; i < 3; i++) {                // 192 rows * 4 cp16 / 256 thr
            int id = tid + i * 256;
            int n = id >> 2, col8 = (id & 3) * 8;
            cp16(&Wb[n * XST + col8], &g_wt[(size_t)n * EMB + e0 + col8]);
        }
    };
    auto stsX = [&](const float4 xr[2], int bs) {
        __half* Xb = Xs + bs * 64 * XST;
#pragma unroll
        for (int i = 0; i < 2; i++) {
            int row = i ? xrow1 : xrow0;
            __half* d = &Xb[row * XST + xgrp];
            *(__half2*)&d[xpa]     = __floats2half2_rn(xr[i].x, xr[i].y);
            *(__half2*)&d[xpa + 4] = __floats2half2_rn(xr[i].z, xr[i].w);
        }
    };

    float acc[2][6][4];
#pragma unroll
    for (int i = 0; i < 2; i++)
#pragma unroll
        for (int j = 0; j < 6; j++)
#pragma unroll
            for (int c = 0; c < 4; c++) acc[i][j][c] = 0.0f;

    float4 xr[2];
    xr[0] = *(const float4*)&x[(size_t)(m0 + xrow0) * EMB + xcol];
    xr[1] = *(const float4*)&x[(size_t)(m0 + xrow1) * EMB + xcol];
    issueW(0, 0);
    CP_COMMIT();

    const int NST = EMB / 32;
    for (int t = 0; t < NST; t++) {
        const int buf = t & 1;
        __syncthreads();
        stsX(xr, buf);
        if (t + 1 < NST) {
            const int e0 = (t + 1) * 32;
            xr[0] = *(const float4*)&x[(size_t)(m0 + xrow0) * EMB + e0 + xcol];
            xr[1] = *(const float4*)&x[(size_t)(m0 + xrow1) * EMB + e0 + xcol];
            issueW(t + 1, buf ^ 1);
        }
        CP_COMMIT();
        CP_WAIT1();
        __syncthreads();

        const __half* Xb = Xs + buf * 64 * XST;
        const __half* Wb = Wsm + buf * 192 * XST;
#pragma unroll
        for (int ks = 0; ks < 2; ks++) {             // two k16 groups in BK=32
            const int ko = ks * 16 + 4 * t4;
            unsigned a[2][4];
#pragma unroll
            for (int mt = 0; mt < 2; mt++) {
                int r = mw * 32 + mt * 16 + g;
                uint2 p0 = *(const uint2*)&Xb[r * XST + ko];
                uint2 p1 = *(const uint2*)&Xb[(r + 8) * XST + ko];
                a[mt][0] = p0.x; a[mt][2] = p0.y;
                a[mt][1] = p1.x; a[mt][3] = p1.y;
            }
#pragma unroll
            for (int nt = 0; nt < 6; nt++) {
                int n = nw * 48 + nt * 8 + g;
                uint2 wb2 = *(const uint2*)&Wb[n * XST + ko];
                unsigned b[2] = {wb2.x, wb2.y};
                mma_f16(acc[0][nt], a[0], b);
                mma_f16(acc[1][nt], a[1], b);
            }
        }
    }

    // Epilogue: bias add (fp32) -> fp16 -> permuted stores
#pragma unroll
    for (int mt = 0; mt < 2; mt++) {
        const int r0 = m0 + mw * 32 + mt * 16 + g;
        const int bidx = r0 >> 11;
        // token positions within 16-group for V^T (tok&15 = g and g+8)
        const int tpos0 = (g & 1) ? (2 * g - 1) : (2 * g);       // perm16(g)
        const int tpos1 = (g & 1) ? (2 * g + 1) : (2 * g + 2);   // perm16(g+8)
        const int tgrp  = (r0 & (SEQ - 1)) & ~15;
#pragma unroll
        for (int nt = 0; nt < 6; nt++) {
            const int ncol = nw * 48 + nt * 8 + t4 * 2;
            const float b0 = sbias[ncol], b1 = sbias[ncol + 1];
            const float v00 = acc[mt][nt][0] + b0;
            const float v01 = acc[mt][nt][1] + b1;
            const float v10 = acc[mt][nt][2] + b0;
            const float v11 = acc[mt][nt][3] + b1;
            if (ncol < 128) {
                __half* dst = (ncol < 64) ? g_q : g_k;
                const int nl = ncol & 63;
                const int pos = (nl & ~15) + 4 * t4 + 2 * (nt & 1);
                *(__half2*)&dst[(size_t)r0 * HS + pos]       = __floats2half2_rn(v00, v01);
                *(__half2*)&dst[(size_t)(r0 + 8) * HS + pos] = __floats2half2_rn(v10, v11);
            } else {
                const int h = ncol - 128;
                __half* base = g_vt + ((size_t)bidx * HS) * SEQ + tgrp;
                base[(size_t)h * SEQ + tpos0]       = __float2half_rn(v00);
                base[(size_t)(h + 1) * SEQ + tpos0] = __float2half_rn(v01);
                base[(size_t)h * SEQ + tpos1]       = __float2half_rn(v10);
                base[(size_t)(h + 1) * SEQ + tpos1] = __float2half_rn(v11);
            }
        }
    }
}

// ---------------------------------------------------------------------------
// Kernel 2: causal flash attention partials, fp16 MMA, split-KV 4-way.
// Smem (halves, stride 80): P/Q slab + K double buffer + V = 4 slabs = 40KB
// -> 4 CTAs/SM.
// ---------------------------------------------------------------------------
#define AST 80   // halves per 64-half row (conflict-free)
#define ATTN_SMEM (4 * 64 * AST * 2)

__global__ __launch_bounds__(128, 4) void attn_part_kernel()
{
    extern __shared__ char smraw[];
    __half* Qs = (__half*)smraw;          // [64][80]; reused per-warp as P
    __half* Ks = Qs + 64 * AST;           // [2][64][80] rows=token, cols=h_perm16
    __half* Vs = Qs + 3 * 64 * AST;       // [64][80]    rows=h, cols=tok_perm16

    const int b  = blockIdx.y;
    const int bx = blockIdx.x;
    const int qt = NQT - 1 - (bx >> 2);
    const int s  = bx & 3;
    const int n  = qt + 1;
    const int c  = (n + 3) >> 2;
    const int lo = min(n, s * c);
    const int hi = min(n, lo + c);
    const int q0 = qt * 64;
    const int tid  = threadIdx.x;
    const int warp = tid >> 5;
    const int lane = tid & 31;
    const int g  = lane >> 2;
    const int t4 = lane & 3;

    float* opart = g_opart + ((size_t)s * MTOT + (size_t)b * SEQ + q0) * HS;
    float* mpart = g_mpart + s * MTOT + b * SEQ + q0;
    float* lpart = g_lpart + s * MTOT + b * SEQ + q0;

    if (lo >= hi) {
        if (tid < 64) { mpart[tid] = -1e30f; lpart[tid] = 0.0f; }
        return;
    }

    const __half* qg  = g_q + ((size_t)b * SEQ + q0) * HS;
    const __half* kg  = g_k + (size_t)b * SEQ * HS;
    const __half* vtg = g_vt + (size_t)b * HS * SEQ;

    auto issueK = [&](int kt, int bs) {
        __half* Kb = Ks + bs * 64 * AST;
#pragma unroll
        for (int i = 0; i < 4; i++) {                // 64 rows * 8 cp16 / 128 thr
            int id = tid + i * 128;
            int row = id >> 3, col8 = (id & 7) * 8;
            cp16(&Kb[row * AST + col8], &kg[(size_t)(kt * 64 + row) * HS + col8]);
        }
    };
    auto issueV = [&](int kt) {
#pragma unroll
        for (int i = 0; i < 4; i++) {
            int id = tid + i * 128;
            int row = id >> 3, col8 = (id & 7) * 8;
            cp16(&Vs[row * AST + col8], &vtg[(size_t)row * SEQ + kt * 64 + col8]);
        }
    };

    // Prologue: stage Q, then K(lo)
#pragma unroll
    for (int i = 0; i < 4; i++) {
        int id = tid + i * 128;
        int row = id >> 3, col8 = (id & 7) * 8;
        cp16(&Qs[row * AST + col8], &qg[(size_t)row * HS + col8]);
    }
    CP_COMMIT();
    issueK(lo, 0);
    CP_COMMIT();
    CP_WAIT0();
    __syncthreads();

    const int qr = warp * 16 + g;
    unsigned qf[4][4];
#pragma unroll
    for (int ks = 0; ks < 4; ks++) {
        const int ko = ks * 16 + 4 * t4;
        uint2 p0 = *(const uint2*)&Qs[qr * AST + ko];
        uint2 p1 = *(const uint2*)&Qs[(qr + 8) * AST + ko];
        qf[ks][0] = p0.x; qf[ks][2] = p0.y;
        qf[ks][1] = p1.x; qf[ks][3] = p1.y;
    }

    float o[8][4];
#pragma unroll
    for (int nt = 0; nt < 8; nt++)
#pragma unroll
        for (int cc = 0; cc < 4; cc++) o[nt][cc] = 0.0f;
    float mrow0 = -1e30f, mrow1 = -1e30f, lsum0 = 0.0f, lsum1 = 0.0f;

    for (int kt = lo; kt < hi; kt++) {
        const int kb = (kt - lo) & 1;
        if (kt > lo) CP_WAIT0();   // K(kt) resident
        __syncthreads();           // prev PV done: V/P slabs reusable

        issueV(kt);                // needed only after S+softmax
        CP_COMMIT();
        if (kt + 1 < hi) issueK(kt + 1, kb ^ 1);
        CP_COMMIT();

        const __half* Kb = Ks + kb * 64 * AST;

        // S = Q K^T
        float sc[8][4];
#pragma unroll
        for (int nt = 0; nt < 8; nt++)
#pragma unroll
            for (int cc = 0; cc < 4; cc++) sc[nt][cc] = 0.0f;
#pragma unroll
        for (int ks = 0; ks < 4; ks++) {
            const int ko = ks * 16 + 4 * t4;
#pragma unroll
            for (int nt = 0; nt < 8; nt++) {
                uint2 kb2 = *(const uint2*)&Kb[(nt * 8 + g) * AST + ko];
                unsigned bfr[2] = {kb2.x, kb2.y};
                mma_f16(sc[nt], qf[ks], bfr);
            }
        }

        if (kt == qt) {   // causal mask, diagonal tile only
#pragma unroll
            for (int nt = 0; nt < 8; nt++) {
                int col = nt * 8 + t4 * 2;
#pragma unroll
                for (int cc = 0; cc < 4; cc++) {
                    int ccol = col + (cc & 1);
                    int rr = qr + ((cc >> 1) << 3);
                    if (ccol > rr) sc[nt][cc] = -1e30f;
                }
            }
        }

        // online softmax (base-2)
        float mt0 = -1e30f, mt1 = -1e30f;
#pragma unroll
        for (int nt = 0; nt < 8; nt++) {
            mt0 = fmaxf(mt0, fmaxf(sc[nt][0], sc[nt][1]));
            mt1 = fmaxf(mt1, fmaxf(sc[nt][2], sc[nt][3]));
        }
#pragma unroll
        for (int off = 1; off <= 2; off <<= 1) {
            mt0 = fmaxf(mt0, __shfl_xor_sync(0xffffffffu, mt0, off));
            mt1 = fmaxf(mt1, __shfl_xor_sync(0xffffffffu, mt1, off));
        }
        float mnew0 = fmaxf(mrow0, mt0), mnew1 = fmaxf(mrow1, mt1);
        float alpha0 = fast_exp2(mrow0 - mnew0), alpha1 = fast_exp2(mrow1 - mnew1);
        float lt0 = 0.0f, lt1 = 0.0f;
#pragma unroll
        for (int nt = 0; nt < 8; nt++) {
            sc[nt][0] = fast_exp2(sc[nt][0] - mnew0);
            sc[nt][1] = fast_exp2(sc[nt][1] - mnew0);
            sc[nt][2] = fast_exp2(sc[nt][2] - mnew1);
            sc[nt][3] = fast_exp2(sc[nt][3] - mnew1);
            lt0 += sc[nt][0] + sc[nt][1];
            lt1 += sc[nt][2] + sc[nt][3];
        }
#pragma unroll
        for (int off = 1; off <= 2; off <<= 1) {
            lt0 += __shfl_xor_sync(0xffffffffu, lt0, off);
            lt1 += __shfl_xor_sync(0xffffffffu, lt1, off);
        }
        mrow0 = mnew0; mrow1 = mnew1;
        lsum0 = lsum0 * alpha0 + lt0;
        lsum1 = lsum1 * alpha1 + lt1;
#pragma unroll
        for (int nt = 0; nt < 8; nt++) {
            o[nt][0] *= alpha0; o[nt][1] *= alpha0;
            o[nt][2] *= alpha1; o[nt][3] *= alpha1;
        }

        // P (fp16) into this warp's private Q rows, token-perm16 columns
        __half* Pw = Qs + (warp * 16) * AST;
#pragma unroll
        for (int nt = 0; nt < 8; nt++) {
            const int pos = (nt >> 1) * 16 + 4 * t4 + 2 * (nt & 1);
            *(__half2*)&Pw[g * AST + pos]       = __floats2half2_rn(sc[nt][0], sc[nt][1]);
            *(__half2*)&Pw[(g + 8) * AST + pos] = __floats2half2_rn(sc[nt][2], sc[nt][3]);
        }
        __syncwarp();

        CP_WAIT1();        // V(kt) resident
        __syncthreads();

        // O += P V
#pragma unroll
        for (int ks = 0; ks < 4; ks++) {
            const int ko = ks * 16 + 4 * t4;
            uint2 p0 = *(const uint2*)&Pw[g * AST + ko];
            uint2 p1 = *(const uint2*)&Pw[(g + 8) * AST + ko];
            unsigned pa[4] = {p0.x, p1.x, p0.y, p1.y};
#pragma unroll
            for (int nt = 0; nt < 8; nt++) {
                uint2 vv = *(const uint2*)&Vs[(nt * 8 + g) * AST + ko];
                unsigned vb2[2] = {vv.x, vv.y};
                mma_f16(o[nt], pa, vb2);
            }
        }
    }

    // Epilogue (fp32 partials; h-dim unpermuted)
#pragma unroll
    for (int nt = 0; nt < 8; nt++) {
        int col = nt * 8 + t4 * 2;
        *(float2*)&opart[(size_t)qr * HS + col]       = make_float2(o[nt][0], o[nt][1]);
        *(float2*)&opart[(size_t)(qr + 8) * HS + col] = make_float2(o[nt][2], o[nt][3]);
    }
    if (t4 == 0) {
        mpart[qr]     = mrow0;  lpart[qr]     = lsum0;
        mpart[qr + 8] = mrow1;  lpart[qr + 8] = lsum1;
    }
}

// ---------------------------------------------------------------------------
// Kernel 3: combine the four splits.
// ---------------------------------------------------------------------------
__global__ __launch_bounds__(256) void combine_kernel(float* __restrict__ out)
{
    int i = blockIdx.x * blockDim.x + threadIdx.x;
    int row = i >> 4;
    int col = (i & 15) * 4;

    float ms[NSPLIT], ls[NSPLIT];
    float m = -1e30f;
#pragma unroll
    for (int s = 0; s < NSPLIT; s++) {
        ms[s] = g_mpart[s * MTOT + row];
        ls[s] = g_lpart[s * MTOT + row];
        m = fmaxf(m, ms[s]);
    }
    float w[NSPLIT], L = 0.0f;
#pragma unroll
    for (int s = 0; s < NSPLIT; s++) {
        w[s] = fast_exp2(ms[s] - m);
        L += ls[s] * w[s];
    }
    float inv = 1.0f / L;

    float4 r = make_float4(0.f, 0.f, 0.f, 0.f);
#pragma unroll
    for (int s = 0; s < NSPLIT; s++) {
        if (ls[s] > 0.0f) {
            float sw = w[s] * inv;
            float4 a = *(const float4*)&g_opart[((size_t)s * MTOT + row) * HS + col];
            r.x += a.x * sw; r.y += a.y * sw;
            r.z += a.z * sw; r.w += a.w * sw;
        }
    }
    *(float4*)&out[(size_t)row * HS + col] = r;
}

// ---------------------------------------------------------------------------
extern "C" void kernel_launch(void* const* d_in, const int* in_sizes, int n_in,
                              void* d_out, int out_size)
{
    const float* x  = (const float*)d_in[0];
    const float* Wq = (const float*)d_in[1];
    const float* bq = (const float*)d_in[2];
    const float* Wk = (const float*)d_in[3];
    const float* bk = (const float*)d_in[4];
    const float* Wv = (const float*)d_in[5];
    const float* bv = (const float*)d_in[6];
    float* out = (float*)d_out;

    wconv_kernel<<<192, 256>>>(Wq, Wk, Wv);

    cudaFuncSetAttribute(proj_kernel,
                         cudaFuncAttributeMaxDynamicSharedMemorySize, PROJ_SMEM);
    proj_kernel<<<MTOT / 64, 256, PROJ_SMEM>>>(x, bq, bk, bv);

    cudaFuncSetAttribute(attn_part_kernel,
                         cudaFuncAttributeMaxDynamicSharedMemorySize, ATTN_SMEM);
    dim3 gattn(NQT * NSPLIT, BATCH);
    attn_part_kernel<<<gattn, 128, ATTN_SMEM>>>();

    combine_kernel<<<(MTOT * HS / 4) / 256, 256>>>(out);
}

// round 14
// speedup vs baseline: 7.6517x; 1.0791x over previous
#include <cuda_runtime.h>
#include <cuda_fp16.h>
#include <cstdint>

#define BATCH 8
#define SEQ   2048
#define EMB   1024
#define HS    64
#define MTOT  (BATCH * SEQ)   // 16384
#define NQT   (SEQ / 64)      // 32 q-tiles per batch
#define NSPLIT 4
#define QSCALE (0.125f * 1.44269504f)   // 1/sqrt(64) * log2(e)

// Scratch: fp16 operands in fragment-pair-permuted (16-group) layouts
__device__ __half g_wt[192 * EMB];         // [n][k_perm16], q rows pre-scaled
__device__ __half g_q[MTOT * HS];          // [token][h_perm16], pre-scaled
__device__ __half g_k[MTOT * HS];          // [token][h_perm16]
__device__ __half g_vt[MTOT * HS];         // [b][h][token_perm16]
__device__ float g_opart[NSPLIT * MTOT * HS];
__device__ float g_mpart[NSPLIT * MTOT];
__device__ float g_lpart[NSPLIT * MTOT];

__device__ __forceinline__ float fast_exp2(float x) {
    float y;
    asm("ex2.approx.ftz.f32 %0, %1;" : "=f"(y) : "f"(x));
    return y;
}
__device__ __forceinline__ void mma_f16(float c[4], const unsigned a[4], const unsigned b[2]) {
    asm volatile(
        "mma.sync.aligned.m16n8k16.row.col.f32.f16.f16.f32 "
        "{%0,%1,%2,%3}, {%4,%5,%6,%7}, {%8,%9}, {%0,%1,%2,%3};"
        : "+f"(c[0]), "+f"(c[1]), "+f"(c[2]), "+f"(c[3])
        : "r"(a[0]), "r"(a[1]), "r"(a[2]), "r"(a[3]), "r"(b[0]), "r"(b[1]));
}
__device__ __forceinline__ void cp16(void* dst_smem, const void* src) {
    unsigned d = (unsigned)__cvta_generic_to_shared(dst_smem);
    asm volatile("cp.async.cg.shared.global [%0], [%1], 16;" :: "r"(d), "l"(src));
}
#define CP_COMMIT() asm volatile("cp.async.commit_group;")
#define CP_WAIT0()  asm volatile("cp.async.wait_group 0;")
#define CP_WAIT1()  asm volatile("cp.async.wait_group 1;")

// perm16: within a 16-group, source offsets {2p,2p+1,2p+8,2p+9} -> {4p..4p+3}
// float4 at 4-aligned offset o (o&15 = 4*hq): halves (x,y) -> pos pa, (z,w) -> pa+4
__device__ __forceinline__ int posA4(int hq) { return ((hq & 1) << 3) | ((hq >> 1) << 1); }

// ---------------------------------------------------------------------------
// Kernel 0: W pre-convert to fp16 perm16 (q rows pre-scaled).
// ---------------------------------------------------------------------------
__global__ __launch_bounds__(256) void wconv_kernel(
    const float* __restrict__ Wq, const float* __restrict__ Wk,
    const float* __restrict__ Wv)
{
    const int n = blockIdx.x;
    const float* src = (n < 64) ? Wq + (size_t)n * EMB
                     : (n < 128) ? Wk + (size_t)(n - 64) * EMB
                                 : Wv + (size_t)(n - 128) * EMB;
    const float s = (n < 64) ? QSCALE : 1.0f;
    const int k = threadIdx.x * 4;
    float4 v = *(const float4*)&src[k];
    const int grp = k & ~15;
    const int pa  = posA4((k & 15) >> 2);
    __half* dst = g_wt + (size_t)n * EMB + grp;
    *(__half2*)&dst[pa]     = __floats2half2_rn(v.x * s, v.y * s);
    *(__half2*)&dst[pa + 4] = __floats2half2_rn(v.z * s, v.w * s);
}

// ---------------------------------------------------------------------------
// Kernel 1: fused QKV projection, fp16 MMA (m16n8k16), fp32 accumulate.
// tile 64(M) x 192(N), BK=64 (16 stages: half the barriers of BK=32).
// 256 threads = 8 warps (2M x 4N). Row stride 80 halves (conflict-free).
// ---------------------------------------------------------------------------
#define PST 80   // halves per BK=64 row
#define PROJ_SMEM ((2 * 64 * PST + 2 * 192 * PST) * 2 + 192 * 4)

__global__ __launch_bounds__(256) void proj_kernel(
    const float* __restrict__ x,
    const float* __restrict__ bq, const float* __restrict__ bk,
    const float* __restrict__ bv)
{
    extern __shared__ char smraw[];
    __half* Xs    = (__half*)smraw;                         // [2][64][80]
    __half* Wsm   = Xs + 2 * 64 * PST;                      // [2][192][80]
    float*  sbias = (float*)(Wsm + 2 * 192 * PST);          // [192]

    const int tid  = threadIdx.x;
    const int warp = tid >> 5;
    const int lane = tid & 31;
    const int g    = lane >> 2;
    const int t4   = lane & 3;
    const int mw   = warp >> 2;
    const int nw   = warp & 3;
    const int m0   = blockIdx.x * 64;

    if (tid < 192)
        sbias[tid] = (tid < 64) ? bq[tid] * QSCALE
                   : (tid < 128 ? bk[tid - 64] : bv[tid - 128]);

    // X: 64 rows x 64 cols fp32 = 1024 float4 / 256 thr = 4 per thread per stage
    auto ldgX = [&](float4 xr[4], int e0) {
#pragma unroll
        for (int i = 0; i < 4; i++) {
            int id = tid + i * 256;
            int row = id >> 4, c4 = id & 15;
            xr[i] = *(const float4*)&x[(size_t)(m0 + row) * EMB + e0 + c4 * 4];
        }
    };
    auto stsX = [&](const float4 xr[4], int bufb) {
        __half* Xb = Xs + bufb * 64 * PST;
#pragma unroll
        for (int i = 0; i < 4; i++) {
            int id = tid + i * 256;
            int row = id >> 4, c4 = id & 15;
            const int col  = c4 * 4;                  // fp32 col within 64
            const int grp  = col & ~15;
            const int pa   = posA4((col & 15) >> 2);
            __half* d = &Xb[row * PST + grp];
            *(__half2*)&d[pa]     = __floats2half2_rn(xr[i].x, xr[i].y);
            *(__half2*)&d[pa + 4] = __floats2half2_rn(xr[i].z, xr[i].w);
        }
    };
    // W: 192 rows x 64 halves = 1536 cp16 / 256 thr = 6 per thread per stage
    auto issueW = [&](int t, int bufb) {
        const int e0 = t * 64;
        __half* Wb = Wsm + bufb * 192 * PST;
#pragma unroll
        for (int i = 0; i < 6; i++) {
            int id = tid + i * 256;
            int n = id >> 3, u = id & 7;
            cp16(&Wb[n * PST + u * 8], &g_wt[(size_t)n * EMB + e0 + u * 8]);
        }
    };

    float acc[2][6][4];
#pragma unroll
    for (int i = 0; i < 2; i++)
#pragma unroll
        for (int j = 0; j < 6; j++)
#pragma unroll
            for (int c = 0; c < 4; c++) acc[i][j][c] = 0.0f;

    float4 xr[4];
    ldgX(xr, 0);
    issueW(0, 0);
    CP_COMMIT();

    const int NST = EMB / 64;   // 16 stages
    for (int t = 0; t < NST; t++) {
        const int buf = t & 1;
        __syncthreads();                 // buffer free (MMA of t-2 done)
        stsX(xr, buf);
        if (t + 1 < NST) {
            ldgX(xr, (t + 1) * 64);
            issueW(t + 1, buf ^ 1);
        }
        CP_COMMIT();
        CP_WAIT1();                      // W(t) resident
        __syncthreads();                 // X(t) STS visible

        const __half* Xb = Xs + buf * 64 * PST;
        const __half* Wb = Wsm + buf * 192 * PST;
#pragma unroll
        for (int ks = 0; ks < 4; ks++) {             // four k16 groups in BK=64
            const int ko = ks * 16 + 4 * t4;
            unsigned a[2][4];
#pragma unroll
            for (int mt = 0; mt < 2; mt++) {
                int r = mw * 32 + mt * 16 + g;
                uint2 p0 = *(const uint2*)&Xb[r * PST + ko];
                uint2 p1 = *(const uint2*)&Xb[(r + 8) * PST + ko];
                a[mt][0] = p0.x; a[mt][2] = p0.y;
                a[mt][1] = p1.x; a[mt][3] = p1.y;
            }
#pragma unroll
            for (int nt = 0; nt < 6; nt++) {
                int n = nw * 48 + nt * 8 + g;
                uint2 wb2 = *(const uint2*)&Wb[n * PST + ko];
                unsigned b[2] = {wb2.x, wb2.y};
                mma_f16(acc[0][nt], a[0], b);
                mma_f16(acc[1][nt], a[1], b);
            }
        }
    }

    // Epilogue: bias add (fp32) -> fp16 -> permuted stores
#pragma unroll
    for (int mt = 0; mt < 2; mt++) {
        const int r0 = m0 + mw * 32 + mt * 16 + g;
        const int bidx = r0 >> 11;
        const int tpos0 = (g & 1) ? (2 * g - 1) : (2 * g);       // perm16(g)
        const int tpos1 = (g & 1) ? (2 * g + 1) : (2 * g + 2);   // perm16(g+8)
        const int tgrp  = (r0 & (SEQ - 1)) & ~15;
#pragma unroll
        for (int nt = 0; nt < 6; nt++) {
            const int ncol = nw * 48 + nt * 8 + t4 * 2;
            const float b0 = sbias[ncol], b1 = sbias[ncol + 1];
            const float v00 = acc[mt][nt][0] + b0;
            const float v01 = acc[mt][nt][1] + b1;
            const float v10 = acc[mt][nt][2] + b0;
            const float v11 = acc[mt][nt][3] + b1;
            if (ncol < 128) {
                __half* dst = (ncol < 64) ? g_q : g_k;
                const int nl = ncol & 63;
                const int pos = (nl & ~15) + 4 * t4 + 2 * (nt & 1);
                *(__half2*)&dst[(size_t)r0 * HS + pos]       = __floats2half2_rn(v00, v01);
                *(__half2*)&dst[(size_t)(r0 + 8) * HS + pos] = __floats2half2_rn(v10, v11);
            } else {
                const int h = ncol - 128;
                __half* base = g_vt + ((size_t)bidx * HS) * SEQ + tgrp;
                base[(size_t)h * SEQ + tpos0]       = __float2half_rn(v00);
                base[(size_t)(h + 1) * SEQ + tpos0] = __float2half_rn(v01);
                base[(size_t)h * SEQ + tpos1]       = __float2half_rn(v10);
                base[(size_t)(h + 1) * SEQ + tpos1] = __float2half_rn(v11);
            }
        }
    }
}

// ---------------------------------------------------------------------------
// Kernel 2: causal flash attention partials, fp16 MMA, split-KV 4-way.
// Smem (halves, stride 80): P/Q slab + K double buffer + V = 4 slabs = 40KB
// -> 4 CTAs/SM.
// ---------------------------------------------------------------------------
#define AST 80
#define ATTN_SMEM (4 * 64 * AST * 2)

__global__ __launch_bounds__(128, 4) void attn_part_kernel()
{
    extern __shared__ char smraw[];
    __half* Qs = (__half*)smraw;          // [64][80]; reused per-warp as P
    __half* Ks = Qs + 64 * AST;           // [2][64][80] rows=token, cols=h_perm16
    __half* Vs = Qs + 3 * 64 * AST;       // [64][80]    rows=h, cols=tok_perm16

    const int b  = blockIdx.y;
    const int bx = blockIdx.x;
    const int qt = NQT - 1 - (bx >> 2);
    const int s  = bx & 3;
    const int n  = qt + 1;
    const int c  = (n + 3) >> 2;
    const int lo = min(n, s * c);
    const int hi = min(n, lo + c);
    const int q0 = qt * 64;
    const int tid  = threadIdx.x;
    const int warp = tid >> 5;
    const int lane = tid & 31;
    const int g  = lane >> 2;
    const int t4 = lane & 3;

    float* opart = g_opart + ((size_t)s * MTOT + (size_t)b * SEQ + q0) * HS;
    float* mpart = g_mpart + s * MTOT + b * SEQ + q0;
    float* lpart = g_lpart + s * MTOT + b * SEQ + q0;

    if (lo >= hi) {
        if (tid < 64) { mpart[tid] = -1e30f; lpart[tid] = 0.0f; }
        return;
    }

    const __half* qg  = g_q + ((size_t)b * SEQ + q0) * HS;
    const __half* kg  = g_k + (size_t)b * SEQ * HS;
    const __half* vtg = g_vt + (size_t)b * HS * SEQ;

    auto issueK = [&](int kt, int bs) {
        __half* Kb = Ks + bs * 64 * AST;
#pragma unroll
        for (int i = 0; i < 4; i++) {
            int id = tid + i * 128;
            int row = id >> 3, col8 = (id & 7) * 8;
            cp16(&Kb[row * AST + col8], &kg[(size_t)(kt * 64 + row) * HS + col8]);
        }
    };
    auto issueV = [&](int kt) {
#pragma unroll
        for (int i = 0; i < 4; i++) {
            int id = tid + i * 128;
            int row = id >> 3, col8 = (id & 7) * 8;
            cp16(&Vs[row * AST + col8], &vtg[(size_t)row * SEQ + kt * 64 + col8]);
        }
    };

#pragma unroll
    for (int i = 0; i < 4; i++) {
        int id = tid + i * 128;
        int row = id >> 3, col8 = (id & 7) * 8;
        cp16(&Qs[row * AST + col8], &qg[(size_t)row * HS + col8]);
    }
    CP_COMMIT();
    issueK(lo, 0);
    CP_COMMIT();
    CP_WAIT0();
    __syncthreads();

    const int qr = warp * 16 + g;
    unsigned qf[4][4];
#pragma unroll
    for (int ks = 0; ks < 4; ks++) {
        const int ko = ks * 16 + 4 * t4;
        uint2 p0 = *(const uint2*)&Qs[qr * AST + ko];
        uint2 p1 = *(const uint2*)&Qs[(qr + 8) * AST + ko];
        qf[ks][0] = p0.x; qf[ks][2] = p0.y;
        qf[ks][1] = p1.x; qf[ks][3] = p1.y;
    }

    float o[8][4];
#pragma unroll
    for (int nt = 0; nt < 8; nt++)
#pragma unroll
        for (int cc = 0; cc < 4; cc++) o[nt][cc] = 0.0f;
    float mrow0 = -1e30f, mrow1 = -1e30f, lsum0 = 0.0f, lsum1 = 0.0f;

    for (int kt = lo; kt < hi; kt++) {
        const int kb = (kt - lo) & 1;
        if (kt > lo) CP_WAIT0();
        __syncthreads();

        issueV(kt);
        CP_COMMIT();
        if (kt + 1 < hi) issueK(kt + 1, kb ^ 1);
        CP_COMMIT();

        const __half* Kb = Ks + kb * 64 * AST;

        float sc[8][4];
#pragma unroll
        for (int nt = 0; nt < 8; nt++)
#pragma unroll
            for (int cc = 0; cc < 4; cc++) sc[nt][cc] = 0.0f;
#pragma unroll
        for (int ks = 0; ks < 4; ks++) {
            const int ko = ks * 16 + 4 * t4;
#pragma unroll
            for (int nt = 0; nt < 8; nt++) {
                uint2 kb2 = *(const uint2*)&Kb[(nt * 8 + g) * AST + ko];
                unsigned bfr[2] = {kb2.x, kb2.y};
                mma_f16(sc[nt], qf[ks], bfr);
            }
        }

        if (kt == qt) {
#pragma unroll
            for (int nt = 0; nt < 8; nt++) {
                int col = nt * 8 + t4 * 2;
#pragma unroll
                for (int cc = 0; cc < 4; cc++) {
                    int ccol = col + (cc & 1);
                    int rr = qr + ((cc >> 1) << 3);
                    if (ccol > rr) sc[nt][cc] = -1e30f;
                }
            }
        }

        float mt0 = -1e30f, mt1 = -1e30f;
#pragma unroll
        for (int nt = 0; nt < 8; nt++) {
            mt0 = fmaxf(mt0, fmaxf(sc[nt][0], sc[nt][1]));
            mt1 = fmaxf(mt1, fmaxf(sc[nt][2], sc[nt][3]));
        }
#pragma unroll
        for (int off = 1; off <= 2; off <<= 1) {
            mt0 = fmaxf(mt0, __shfl_xor_sync(0xffffffffu, mt0, off));
            mt1 = fmaxf(mt1, __shfl_xor_sync(0xffffffffu, mt1, off));
        }
        float mnew0 = fmaxf(mrow0, mt0), mnew1 = fmaxf(mrow1, mt1);
        float alpha0 = fast_exp2(mrow0 - mnew0), alpha1 = fast_exp2(mrow1 - mnew1);
        float lt0 = 0.0f, lt1 = 0.0f;
#pragma unroll
        for (int nt = 0; nt < 8; nt++) {
            sc[nt][0] = fast_exp2(sc[nt][0] - mnew0);
            sc[nt][1] = fast_exp2(sc[nt][1] - mnew0);
            sc[nt][2] = fast_exp2(sc[nt][2] - mnew1);
            sc[nt][3] = fast_exp2(sc[nt][3] - mnew1);
            lt0 += sc[nt][0] + sc[nt][1];
            lt1 += sc[nt][2] + sc[nt][3];
        }
#pragma unroll
        for (int off = 1; off <= 2; off <<= 1) {
            lt0 += __shfl_xor_sync(0xffffffffu, lt0, off);
            lt1 += __shfl_xor_sync(0xffffffffu, lt1, off);
        }
        mrow0 = mnew0; mrow1 = mnew1;
        lsum0 = lsum0 * alpha0 + lt0;
        lsum1 = lsum1 * alpha1 + lt1;
#pragma unroll
        for (int nt = 0; nt < 8; nt++) {
            o[nt][0] *= alpha0; o[nt][1] *= alpha0;
            o[nt][2] *= alpha1; o[nt][3] *= alpha1;
        }

        __half* Pw = Qs + (warp * 16) * AST;
#pragma unroll
        for (int nt = 0; nt < 8; nt++) {
            const int pos = (nt >> 1) * 16 + 4 * t4 + 2 * (nt & 1);
            *(__half2*)&Pw[g * AST + pos]       = __floats2half2_rn(sc[nt][0], sc[nt][1]);
            *(__half2*)&Pw[(g + 8) * AST + pos] = __floats2half2_rn(sc[nt][2], sc[nt][3]);
        }
        __syncwarp();

        CP_WAIT1();
        __syncthreads();

#pragma unroll
        for (int ks = 0; ks < 4; ks++) {
            const int ko = ks * 16 + 4 * t4;
            uint2 p0 = *(const uint2*)&Pw[g * AST + ko];
            uint2 p1 = *(const uint2*)&Pw[(g + 8) * AST + ko];
            unsigned pa[4] = {p0.x, p1.x, p0.y, p1.y};
#pragma unroll
            for (int nt = 0; nt < 8; nt++) {
                uint2 vv = *(const uint2*)&Vs[(nt * 8 + g) * AST + ko];
                unsigned vb2[2] = {vv.x, vv.y};
                mma_f16(o[nt], pa, vb2);
            }
        }
    }

#pragma unroll
    for (int nt = 0; nt < 8; nt++) {
        int col = nt * 8 + t4 * 2;
        *(float2*)&opart[(size_t)qr * HS + col]       = make_float2(o[nt][0], o[nt][1]);
        *(float2*)&opart[(size_t)(qr + 8) * HS + col] = make_float2(o[nt][2], o[nt][3]);
    }
    if (t4 == 0) {
        mpart[qr]     = mrow0;  lpart[qr]     = lsum0;
        mpart[qr + 8] = mrow1;  lpart[qr + 8] = lsum1;
    }
}

// ---------------------------------------------------------------------------
// Kernel 3: combine the four splits.
// ---------------------------------------------------------------------------
__global__ __launch_bounds__(256) void combine_kernel(float* __restrict__ out)
{
    int i = blockIdx.x * blockDim.x + threadIdx.x;
    int row = i >> 4;
    int col = (i & 15) * 4;

    float ms[NSPLIT], ls[NSPLIT];
    float m = -1e30f;
#pragma unroll
    for (int s = 0; s < NSPLIT; s++) {
        ms[s] = g_mpart[s * MTOT + row];
        ls[s] = g_lpart[s * MTOT + row];
        m = fmaxf(m, ms[s]);
    }
    float w[NSPLIT], L = 0.0f;
#pragma unroll
    for (int s = 0; s < NSPLIT; s++) {
        w[s] = fast_exp2(ms[s] - m);
        L += ls[s] * w[s];
    }
    float inv = 1.0f / L;

    float4 r = make_float4(0.f, 0.f, 0.f, 0.f);
#pragma unroll
    for (int s = 0; s < NSPLIT; s++) {
        if (ls[s] > 0.0f) {
            float sw = w[s] * inv;
            float4 a = *(const float4*)&g_opart[((size_t)s * MTOT + row) * HS + col];
            r.x += a.x * sw; r.y += a.y * sw;
            r.z += a.z * sw; r.w += a.w * sw;
        }
    }
    *(float4*)&out[(size_t)row * HS + col] = r;
}

// ---------------------------------------------------------------------------
extern "C" void kernel_launch(void* const* d_in, const int* in_sizes, int n_in,
                              void* d_out, int out_size)
{
    const float* x  = (const float*)d_in[0];
    const float* Wq = (const float*)d_in[1];
    const float* bq = (const float*)d_in[2];
    const float* Wk = (const float*)d_in[3];
    const float* bk = (const float*)d_in[4];
    const float* Wv = (const float*)d_in[5];
    const float* bv = (const float*)d_in[6];
    float* out = (float*)d_out;

    wconv_kernel<<<192, 256>>>(Wq, Wk, Wv);

    cudaFuncSetAttribute(proj_kernel,
                         cudaFuncAttributeMaxDynamicSharedMemorySize, PROJ_SMEM);
    proj_kernel<<<MTOT / 64, 256, PROJ_SMEM>>>(x, bq, bk, bv);

    cudaFuncSetAttribute(attn_part_kernel,
                         cudaFuncAttributeMaxDynamicSharedMemorySize, ATTN_SMEM);
    dim3 gattn(NQT * NSPLIT, BATCH);
    attn_part_kernel<<<gattn, 128, ATTN_SMEM>>>();

    combine_kernel<<<(MTOT * HS / 4) / 256, 256>>>(out);
}